// round 1
// baseline (speedup 1.0000x reference)
#include <cuda_runtime.h>
#include <math.h>

#define N_TOK 4096
#define D_MODEL 256
#define H_HEADS 8
#define HD 32
#define QKV_W 768

// ---------------- scratch (device globals; no allocation allowed) ----------
__device__ float g_qkv[N_TOK * QKV_W];    // [N, 3D]  (q | k | v)
__device__ float g_attn[N_TOK * D_MODEL]; // attention output
__device__ float g_proj[N_TOK * D_MODEL]; // out-proj result

// ---------------- generic tiled SGEMM: C[M,N] = A[M,K] @ B[N,K]^T + bias ---
#define BM 64
#define BN 64
#define BK 32

__global__ void sgemm_bias_kernel(const float* __restrict__ A,
                                  const float* __restrict__ B,
                                  const float* __restrict__ bias,
                                  float* __restrict__ C,
                                  int M, int N, int K) {
    __shared__ float As[BK][BM + 1];
    __shared__ float Bs[BK][BN + 1];

    const int t = threadIdx.x;            // 256 threads
    const int tx = t & 15;                // 16 x 16 thread grid
    const int ty = t >> 4;
    const int m0 = blockIdx.y * BM;
    const int n0 = blockIdx.x * BN;

    float acc[4][4];
#pragma unroll
    for (int i = 0; i < 4; i++)
#pragma unroll
        for (int j = 0; j < 4; j++) acc[i][j] = 0.f;

    for (int k0 = 0; k0 < K; k0 += BK) {
        // load A tile [BM x BK] -> As[k][m]  (coalesced on k)
#pragma unroll
        for (int i = 0; i < (BM * BK) / 256; i++) {
            int idx = t + i * 256;
            int k = idx & (BK - 1);
            int m = idx >> 5;
            As[k][m] = A[(size_t)(m0 + m) * K + k0 + k];
        }
#pragma unroll
        for (int i = 0; i < (BN * BK) / 256; i++) {
            int idx = t + i * 256;
            int k = idx & (BK - 1);
            int n = idx >> 5;
            Bs[k][n] = B[(size_t)(n0 + n) * K + k0 + k];
        }
        __syncthreads();

#pragma unroll
        for (int kk = 0; kk < BK; kk++) {
            float a[4], b[4];
#pragma unroll
            for (int i = 0; i < 4; i++) a[i] = As[kk][ty * 4 + i];
#pragma unroll
            for (int j = 0; j < 4; j++) b[j] = Bs[kk][tx * 4 + j];
#pragma unroll
            for (int i = 0; i < 4; i++)
#pragma unroll
                for (int j = 0; j < 4; j++) acc[i][j] = fmaf(a[i], b[j], acc[i][j]);
        }
        __syncthreads();
    }

#pragma unroll
    for (int i = 0; i < 4; i++) {
        int m = m0 + ty * 4 + i;
#pragma unroll
        for (int j = 0; j < 4; j++) {
            int n = n0 + tx * 4 + j;
            C[(size_t)m * N + n] = acc[i][j] + bias[n];
        }
    }
}

// ---------------- flash attention over block-diagonal mask -----------------
// batch_idx is sorted; each row's attention support is a contiguous segment.
#define QT 64
#define KT 64

__device__ __forceinline__ int lb_search(const int* __restrict__ a, int n, int v) {
    int lo = 0, hi = n;
    while (lo < hi) { int mid = (lo + hi) >> 1; if (a[mid] < v) lo = mid + 1; else hi = mid; }
    return lo;
}
__device__ __forceinline__ int ub_search(const int* __restrict__ a, int n, int v) {
    int lo = 0, hi = n;
    while (lo < hi) { int mid = (lo + hi) >> 1; if (a[mid] <= v) lo = mid + 1; else hi = mid; }
    return lo;
}

__global__ void flash_attn_kernel(const float* __restrict__ qkv,
                                  const int* __restrict__ bidx,
                                  float* __restrict__ attn_out) {
    __shared__ float Qs[QT][HD + 1];
    __shared__ float Ks[KT][HD + 1];
    __shared__ float Vs[KT][HD + 1];
    __shared__ float Ps[QT][KT + 1];
    __shared__ int kb[KT];
    __shared__ int qb[QT];

    const int h = blockIdx.y;
    const int q0 = blockIdx.x * QT;
    const int t = threadIdx.x;            // 256 threads
    const int qoff = h * HD;              // q cols
    const int koff = D_MODEL + h * HD;    // k cols
    const int voff = 2 * D_MODEL + h * HD;

    // load Q tile + query batch ids
#pragma unroll
    for (int i = t; i < QT * HD; i += 256) {
        int r = i >> 5, d = i & 31;
        Qs[r][d] = qkv[(size_t)(q0 + r) * QKV_W + qoff + d];
    }
    if (t < QT) qb[t] = bidx[q0 + t];
    __syncthreads();

    const int b_lo = qb[0];
    const int b_hi = qb[QT - 1];
    const int seg_s = lb_search(bidx, N_TOK, b_lo);
    const int seg_e = ub_search(bidx, N_TOK, b_hi);

    const int r = t >> 2;       // query row in tile (4 threads/row)
    const int j = t & 3;        // sub-thread within row
    const int myb = qb[r];
    const float scale = 0.1767766952966369f; // 1/sqrt(32)

    float m = -1e30f, l = 0.f;
    float acc[8];
#pragma unroll
    for (int d = 0; d < 8; d++) acc[d] = 0.f;

    for (int k0 = seg_s; k0 < seg_e; k0 += KT) {
        const int kt = min(KT, seg_e - k0);
        __syncthreads();  // protect Ks/Vs/Ps from previous iteration readers
        // load K,V tile + key batch ids
#pragma unroll
        for (int i = t; i < KT * HD; i += 256) {
            int kk = i >> 5, d = i & 31;
            float kv = 0.f, vv = 0.f;
            if (kk < kt) {
                size_t base = (size_t)(k0 + kk) * QKV_W;
                kv = qkv[base + koff + d];
                vv = qkv[base + voff + d];
            }
            Ks[kk][d] = kv;
            Vs[kk][d] = vv;
        }
        if (t < KT) kb[t] = (t < kt) ? bidx[k0 + t] : -1;
        __syncthreads();

        // scores: this thread -> keys j, j+4, ..., j+60
        float s[16];
        float tmax = -1e30f;
#pragma unroll
        for (int ii = 0; ii < 16; ii++) {
            int k = j + ii * 4;
            float sv = 0.f;
#pragma unroll
            for (int d = 0; d < HD; d++) sv = fmaf(Qs[r][d], Ks[k][d], sv);
            sv *= scale;
            if (k >= kt || kb[k] != myb) sv = -1e30f;
            s[ii] = sv;
            tmax = fmaxf(tmax, sv);
        }
        // row-max across the 4 sibling lanes (consecutive lanes within warp)
        tmax = fmaxf(tmax, __shfl_xor_sync(0xffffffffu, tmax, 1));
        tmax = fmaxf(tmax, __shfl_xor_sync(0xffffffffu, tmax, 2));
        const float mnew = fmaxf(m, tmax);
        const float alpha = __expf(m - mnew);

        float lsum = 0.f;
#pragma unroll
        for (int ii = 0; ii < 16; ii++) {
            float p = (s[ii] < -1e29f) ? 0.f : __expf(s[ii] - mnew);
            Ps[r][j + ii * 4] = p;
            lsum += p;
        }
        lsum += __shfl_xor_sync(0xffffffffu, lsum, 1);
        lsum += __shfl_xor_sync(0xffffffffu, lsum, 2);
        l = l * alpha + lsum;
        m = mnew;

#pragma unroll
        for (int d = 0; d < 8; d++) acc[d] *= alpha;
        __syncthreads();  // Ps fully written

        // PV: this thread -> row r, dims [j*8, j*8+8)
        const int dbase = j * 8;
#pragma unroll 8
        for (int k = 0; k < KT; k++) {
            float p = Ps[r][k];
#pragma unroll
            for (int d = 0; d < 8; d++) acc[d] = fmaf(p, Vs[k][dbase + d], acc[d]);
        }
    }

    const float inv_l = (l > 0.f) ? (1.f / l) : 0.f;
    const int n = q0 + r;
#pragma unroll
    for (int d = 0; d < 8; d++)
        attn_out[(size_t)n * D_MODEL + h * HD + j * 8 + d] = acc[d] * inv_l;
}

// ---------------- residual + LayerNorm ------------------------------------
__global__ void resid_ln_kernel(const float* __restrict__ x,
                                const float* __restrict__ proj,
                                const float* __restrict__ gamma,
                                const float* __restrict__ beta,
                                float* __restrict__ out) {
    __shared__ float red[256];
    const int n = blockIdx.x;
    const int c = threadIdx.x;
    const size_t idx = (size_t)n * D_MODEL + c;

    float v = x[idx] + proj[idx];

    // mean
    red[c] = v;
    __syncthreads();
    for (int s = 128; s > 0; s >>= 1) {
        if (c < s) red[c] += red[c + s];
        __syncthreads();
    }
    const float mean = red[0] * (1.f / D_MODEL);
    __syncthreads();

    // variance
    float dvc = v - mean;
    red[c] = dvc * dvc;
    __syncthreads();
    for (int s = 128; s > 0; s >>= 1) {
        if (c < s) red[c] += red[c + s];
        __syncthreads();
    }
    const float var = red[0] * (1.f / D_MODEL);

    out[idx] = dvc * rsqrtf(var + 1e-5f) * gamma[c] + beta[c];
}

// ---------------- launch ----------------------------------------------------
extern "C" void kernel_launch(void* const* d_in, const int* in_sizes, int n_in,
                              void* d_out, int out_size) {
    const float* slots    = (const float*)d_in[0];  // [1, N, D]
    const int*   batch_ix = (const int*)d_in[1];    // [N]
    const float* w_in     = (const float*)d_in[2];  // [3D, D]
    const float* b_in     = (const float*)d_in[3];  // [3D]
    const float* w_out    = (const float*)d_in[4];  // [D, D]
    const float* b_out    = (const float*)d_in[5];  // [D]
    const float* ln_gamma = (const float*)d_in[6];  // [D]
    const float* ln_beta  = (const float*)d_in[7];  // [D]
    float* out = (float*)d_out;

    float* qkv;  cudaGetSymbolAddress((void**)&qkv,  g_qkv);
    float* attn; cudaGetSymbolAddress((void**)&attn, g_attn);
    float* proj; cudaGetSymbolAddress((void**)&proj, g_proj);

    // 1) QKV projection: qkv[N, 768] = slots @ w_in^T + b_in
    {
        dim3 grid(QKV_W / BN, N_TOK / BM);
        sgemm_bias_kernel<<<grid, 256>>>(slots, w_in, b_in, qkv,
                                         N_TOK, QKV_W, D_MODEL);
    }
    // 2) block-diagonal flash attention
    {
        dim3 grid(N_TOK / QT, H_HEADS);
        flash_attn_kernel<<<grid, 256>>>(qkv, batch_ix, attn);
    }
    // 3) out projection: proj[N, 256] = attn @ w_out^T + b_out
    {
        dim3 grid(D_MODEL / BN, N_TOK / BM);
        sgemm_bias_kernel<<<grid, 256>>>(attn, w_out, b_out, proj,
                                         N_TOK, D_MODEL, D_MODEL);
    }
    // 4) residual + LayerNorm
    resid_ln_kernel<<<N_TOK, 256>>>(slots, proj, ln_gamma, ln_beta, out);
}

// round 2
// speedup vs baseline: 1.4402x; 1.4402x over previous
#include <cuda_runtime.h>
#include <math.h>
#include <stdint.h>

#define N_TOK 4096
#define D_MODEL 256
#define H_HEADS 8
#define HD 32
#define QKV_W 768

// ---------------- scratch (device globals; no allocation allowed) ----------
__device__ float g_qkv[N_TOK * QKV_W];    // [N, 3D]  (q | k | v)
__device__ float g_attn[N_TOK * D_MODEL]; // attention output
__device__ float g_res[N_TOK * D_MODEL];  // out-proj + residual (pre-LN)

// =================== tf32 helpers ==========================================
__device__ __forceinline__ uint32_t f2tf32(float f) {
    uint32_t r;
    asm("cvt.rna.tf32.f32 %0, %1;" : "=r"(r) : "f"(f));
    return r;
}

__device__ __forceinline__ void mma_tf32(float& d0, float& d1, float& d2, float& d3,
                                         uint32_t a0, uint32_t a1, uint32_t a2, uint32_t a3,
                                         uint32_t b0, uint32_t b1) {
    asm volatile("mma.sync.aligned.m16n8k8.row.col.f32.tf32.tf32.f32 "
                 "{%0,%1,%2,%3}, {%4,%5,%6,%7}, {%8,%9}, {%0,%1,%2,%3};"
                 : "+f"(d0), "+f"(d1), "+f"(d2), "+f"(d3)
                 : "r"(a0), "r"(a1), "r"(a2), "r"(a3), "r"(b0), "r"(b1));
}

// =================== tf32 GEMM: C[M,N] = A[M,K] @ B[N,K]^T + bias (+resid) ==
// Block tile 128x64, 8 warps (4x2), warp tile 32x32 (2x4 mma tiles), BK=32.
#define GBM 128
#define GBN 64
#define GBK 32
#define GPAD 4   // smem row stride = GBK + GPAD = 36 floats -> conflict-free frags

__global__ void gemm_tf32_kernel(const float* __restrict__ A,
                                 const float* __restrict__ B,
                                 const float* __restrict__ bias,
                                 const float* __restrict__ resid,
                                 float* __restrict__ C,
                                 int M, int N, int K) {
    __shared__ float As[GBM][GBK + GPAD];
    __shared__ float Bs[GBN][GBK + GPAD];

    const int t = threadIdx.x;            // 256 threads
    const int wid = t >> 5;
    const int lane = t & 31;
    const int g = lane >> 2;              // groupID (0..7)
    const int tq = lane & 3;              // thread-in-group (0..3)
    const int wm = (wid & 3) * 32;        // warp row offset in block tile
    const int wn = (wid >> 2) * 32;       // warp col offset
    const int m0 = blockIdx.y * GBM;
    const int n0 = blockIdx.x * GBN;

    float acc[2][4][4];
#pragma unroll
    for (int mi = 0; mi < 2; mi++)
#pragma unroll
        for (int ni = 0; ni < 4; ni++)
#pragma unroll
            for (int c = 0; c < 4; c++) acc[mi][ni][c] = 0.f;

    for (int k0 = 0; k0 < K; k0 += GBK) {
        // load A tile 128x32 (4 float4 / thread), convert to tf32 bits
#pragma unroll
        for (int i = 0; i < 4; i++) {
            int fi = t + i * 256;                 // 0..1023 float4 index
            int row = fi >> 3;
            int c4 = fi & 7;
            float4 v = *(const float4*)&A[(size_t)(m0 + row) * K + k0 + c4 * 4];
            float* dst = &As[row][c4 * 4];
            dst[0] = __uint_as_float(f2tf32(v.x));
            dst[1] = __uint_as_float(f2tf32(v.y));
            dst[2] = __uint_as_float(f2tf32(v.z));
            dst[3] = __uint_as_float(f2tf32(v.w));
        }
        // load B tile 64x32 (2 float4 / thread)
#pragma unroll
        for (int i = 0; i < 2; i++) {
            int fi = t + i * 256;
            int row = fi >> 3;
            int c4 = fi & 7;
            float4 v = *(const float4*)&B[(size_t)(n0 + row) * K + k0 + c4 * 4];
            float* dst = &Bs[row][c4 * 4];
            dst[0] = __uint_as_float(f2tf32(v.x));
            dst[1] = __uint_as_float(f2tf32(v.y));
            dst[2] = __uint_as_float(f2tf32(v.z));
            dst[3] = __uint_as_float(f2tf32(v.w));
        }
        __syncthreads();

#pragma unroll
        for (int ks = 0; ks < GBK / 8; ks++) {
            const int kb = ks * 8;
            uint32_t a[2][4];
#pragma unroll
            for (int mi = 0; mi < 2; mi++) {
                int r0 = wm + mi * 16 + g;
                a[mi][0] = __float_as_uint(As[r0][kb + tq]);
                a[mi][1] = __float_as_uint(As[r0 + 8][kb + tq]);
                a[mi][2] = __float_as_uint(As[r0][kb + tq + 4]);
                a[mi][3] = __float_as_uint(As[r0 + 8][kb + tq + 4]);
            }
#pragma unroll
            for (int ni = 0; ni < 4; ni++) {
                int bc = wn + ni * 8 + g;
                uint32_t b0 = __float_as_uint(Bs[bc][kb + tq]);
                uint32_t b1 = __float_as_uint(Bs[bc][kb + tq + 4]);
#pragma unroll
                for (int mi = 0; mi < 2; mi++)
                    mma_tf32(acc[mi][ni][0], acc[mi][ni][1], acc[mi][ni][2], acc[mi][ni][3],
                             a[mi][0], a[mi][1], a[mi][2], a[mi][3], b0, b1);
            }
        }
        __syncthreads();
    }

    // epilogue: bias (+resid)
#pragma unroll
    for (int mi = 0; mi < 2; mi++) {
#pragma unroll
        for (int ni = 0; ni < 4; ni++) {
            int col = n0 + wn + ni * 8 + 2 * tq;
            int r0 = m0 + wm + mi * 16 + g;
            int r1 = r0 + 8;
            float bx = bias[col], by = bias[col + 1];
            float2 v0 = make_float2(acc[mi][ni][0] + bx, acc[mi][ni][1] + by);
            float2 v1 = make_float2(acc[mi][ni][2] + bx, acc[mi][ni][3] + by);
            if (resid) {
                float2 rr0 = *(const float2*)&resid[(size_t)r0 * N + col];
                float2 rr1 = *(const float2*)&resid[(size_t)r1 * N + col];
                v0.x += rr0.x; v0.y += rr0.y;
                v1.x += rr1.x; v1.y += rr1.y;
            }
            *(float2*)&C[(size_t)r0 * N + col] = v0;
            *(float2*)&C[(size_t)r1 * N + col] = v1;
        }
    }
}

// ================= flash attention over block-diagonal mask =================
// batch_idx is sorted; each row's attention support is a contiguous segment.
#define QT 64
#define KT 64
#define KPAD 4   // K/V rows padded to 36 floats

__device__ __forceinline__ int lb_search(const int* __restrict__ a, int n, int v) {
    int lo = 0, hi = n;
    while (lo < hi) { int mid = (lo + hi) >> 1; if (a[mid] < v) lo = mid + 1; else hi = mid; }
    return lo;
}
__device__ __forceinline__ int ub_search(const int* __restrict__ a, int n, int v) {
    int lo = 0, hi = n;
    while (lo < hi) { int mid = (lo + hi) >> 1; if (a[mid] <= v) lo = mid + 1; else hi = mid; }
    return lo;
}

__global__ void flash_attn_kernel(const float* __restrict__ qkv,
                                  const int* __restrict__ bidx,
                                  float* __restrict__ attn_out) {
    __shared__ float Ks[KT][HD + KPAD];
    __shared__ float Vs[KT][HD + KPAD];
    __shared__ float Ps[QT][KT + 1];
    __shared__ int kb[KT];
    __shared__ int qb[QT];

    const int h = blockIdx.y;
    const int q0 = blockIdx.x * QT;
    const int t = threadIdx.x;            // 256 threads
    const int r = t >> 2;                 // query row in tile
    const int j = t & 3;                  // sub-thread within row
    const int koff = D_MODEL + h * HD;
    const int voff = 2 * D_MODEL + h * HD;

    if (t < QT) qb[t] = bidx[q0 + t];

    // Q row into registers (4 threads per row hold redundant copies)
    float4 q[8];
    {
        const float4* qptr = (const float4*)&qkv[(size_t)(q0 + r) * QKV_W + h * HD];
#pragma unroll
        for (int i = 0; i < 8; i++) q[i] = qptr[i];
    }
    __syncthreads();

    const int seg_s = lb_search(bidx, N_TOK, qb[0]);
    const int seg_e = ub_search(bidx, N_TOK, qb[QT - 1]);
    const int myb = qb[r];
    const float scale = 0.1767766952966369f; // 1/sqrt(32)

    float m = -1e30f, l = 0.f;
    float acc[8];
#pragma unroll
    for (int d = 0; d < 8; d++) acc[d] = 0.f;

    for (int k0 = seg_s; k0 < seg_e; k0 += KT) {
        const int kt = min(KT, seg_e - k0);
        __syncthreads();
        // load K,V tiles: 512 float4 each, 2 per thread per tile
#pragma unroll
        for (int i = 0; i < 2; i++) {
            int fi = t + i * 256;
            int kk = fi >> 3;
            int c4 = fi & 7;
            float4 kv = make_float4(0.f, 0.f, 0.f, 0.f);
            float4 vv = make_float4(0.f, 0.f, 0.f, 0.f);
            if (kk < kt) {
                size_t base = (size_t)(k0 + kk) * QKV_W;
                kv = *(const float4*)&qkv[base + koff + c4 * 4];
                vv = *(const float4*)&qkv[base + voff + c4 * 4];
            }
            *(float4*)&Ks[kk][c4 * 4] = kv;
            *(float4*)&Vs[kk][c4 * 4] = vv;
        }
        if (t < KT) kb[t] = (t < kt) ? bidx[k0 + t] : -1;
        __syncthreads();

        // scores: this thread -> keys j, j+4, ..., j+60
        float s[16];
        float tmax = -1e30f;
#pragma unroll
        for (int ii = 0; ii < 16; ii++) {
            int k = j + ii * 4;
            const float4* krow = (const float4*)&Ks[k][0];
            float sv = 0.f;
#pragma unroll
            for (int d4 = 0; d4 < 8; d4++) {
                float4 kv = krow[d4];
                sv = fmaf(q[d4].x, kv.x, sv);
                sv = fmaf(q[d4].y, kv.y, sv);
                sv = fmaf(q[d4].z, kv.z, sv);
                sv = fmaf(q[d4].w, kv.w, sv);
            }
            sv *= scale;
            if (k >= kt || kb[k] != myb) sv = -1e30f;
            s[ii] = sv;
            tmax = fmaxf(tmax, sv);
        }
        tmax = fmaxf(tmax, __shfl_xor_sync(0xffffffffu, tmax, 1));
        tmax = fmaxf(tmax, __shfl_xor_sync(0xffffffffu, tmax, 2));
        const float mnew = fmaxf(m, tmax);
        const float alpha = __expf(m - mnew);

        float lsum = 0.f;
#pragma unroll
        for (int ii = 0; ii < 16; ii++) {
            float p = (s[ii] < -1e29f) ? 0.f : __expf(s[ii] - mnew);
            Ps[r][j + ii * 4] = p;
            lsum += p;
        }
        lsum += __shfl_xor_sync(0xffffffffu, lsum, 1);
        lsum += __shfl_xor_sync(0xffffffffu, lsum, 2);
        l = l * alpha + lsum;
        m = mnew;

#pragma unroll
        for (int d = 0; d < 8; d++) acc[d] *= alpha;
        __syncthreads();  // Ps fully written

        // PV: this thread -> row r, dims [j*8, j*8+8)
        const int dbase = j * 8;
#pragma unroll 8
        for (int k = 0; k < KT; k++) {
            float p = Ps[r][k];
            float4 v0 = *(const float4*)&Vs[k][dbase];
            float4 v1 = *(const float4*)&Vs[k][dbase + 4];
            acc[0] = fmaf(p, v0.x, acc[0]);
            acc[1] = fmaf(p, v0.y, acc[1]);
            acc[2] = fmaf(p, v0.z, acc[2]);
            acc[3] = fmaf(p, v0.w, acc[3]);
            acc[4] = fmaf(p, v1.x, acc[4]);
            acc[5] = fmaf(p, v1.y, acc[5]);
            acc[6] = fmaf(p, v1.z, acc[6]);
            acc[7] = fmaf(p, v1.w, acc[7]);
        }
    }

    const float inv_l = (l > 0.f) ? (1.f / l) : 0.f;
    float* op = &attn_out[(size_t)(q0 + r) * D_MODEL + h * HD + j * 8];
    *(float4*)&op[0] = make_float4(acc[0] * inv_l, acc[1] * inv_l, acc[2] * inv_l, acc[3] * inv_l);
    *(float4*)&op[4] = make_float4(acc[4] * inv_l, acc[5] * inv_l, acc[6] * inv_l, acc[7] * inv_l);
}

// ================= LayerNorm (residual already folded in) ===================
__global__ void ln_kernel(const float* __restrict__ res,
                          const float* __restrict__ gamma,
                          const float* __restrict__ beta,
                          float* __restrict__ out) {
    const int w = threadIdx.x >> 5;
    const int lane = threadIdx.x & 31;
    const int row = blockIdx.x * 8 + w;

    const float4* p = (const float4*)&res[(size_t)row * D_MODEL];
    float4 v0 = p[lane];
    float4 v1 = p[lane + 32];

    float s = v0.x + v0.y + v0.z + v0.w + v1.x + v1.y + v1.z + v1.w;
#pragma unroll
    for (int o = 16; o > 0; o >>= 1) s += __shfl_xor_sync(0xffffffffu, s, o);
    const float mean = s * (1.f / D_MODEL);

    float d0x = v0.x - mean, d0y = v0.y - mean, d0z = v0.z - mean, d0w = v0.w - mean;
    float d1x = v1.x - mean, d1y = v1.y - mean, d1z = v1.z - mean, d1w = v1.w - mean;
    float sq = d0x * d0x + d0y * d0y + d0z * d0z + d0w * d0w
             + d1x * d1x + d1y * d1y + d1z * d1z + d1w * d1w;
#pragma unroll
    for (int o = 16; o > 0; o >>= 1) sq += __shfl_xor_sync(0xffffffffu, sq, o);
    const float rsig = rsqrtf(sq * (1.f / D_MODEL) + 1e-5f);

    const float4* gp = (const float4*)gamma;
    const float4* bp = (const float4*)beta;
    float4 g0 = gp[lane], g1 = gp[lane + 32];
    float4 b0 = bp[lane], b1 = bp[lane + 32];

    float4* op = (float4*)&out[(size_t)row * D_MODEL];
    op[lane] = make_float4(d0x * rsig * g0.x + b0.x, d0y * rsig * g0.y + b0.y,
                           d0z * rsig * g0.z + b0.z, d0w * rsig * g0.w + b0.w);
    op[lane + 32] = make_float4(d1x * rsig * g1.x + b1.x, d1y * rsig * g1.y + b1.y,
                                d1z * rsig * g1.z + b1.z, d1w * rsig * g1.w + b1.w);
}

// ---------------- launch ----------------------------------------------------
extern "C" void kernel_launch(void* const* d_in, const int* in_sizes, int n_in,
                              void* d_out, int out_size) {
    const float* slots    = (const float*)d_in[0];  // [1, N, D]
    const int*   batch_ix = (const int*)d_in[1];    // [N]
    const float* w_in     = (const float*)d_in[2];  // [3D, D]
    const float* b_in     = (const float*)d_in[3];  // [3D]
    const float* w_out    = (const float*)d_in[4];  // [D, D]
    const float* b_out    = (const float*)d_in[5];  // [D]
    const float* ln_gamma = (const float*)d_in[6];  // [D]
    const float* ln_beta  = (const float*)d_in[7];  // [D]
    float* out = (float*)d_out;

    float* qkv;  cudaGetSymbolAddress((void**)&qkv,  g_qkv);
    float* attn; cudaGetSymbolAddress((void**)&attn, g_attn);
    float* res;  cudaGetSymbolAddress((void**)&res,  g_res);

    // 1) QKV projection: qkv[N, 768] = slots @ w_in^T + b_in
    {
        dim3 grid(QKV_W / GBN, N_TOK / GBM);
        gemm_tf32_kernel<<<grid, 256>>>(slots, w_in, b_in, nullptr, qkv,
                                        N_TOK, QKV_W, D_MODEL);
    }
    // 2) block-diagonal flash attention
    {
        dim3 grid(N_TOK / QT, H_HEADS);
        flash_attn_kernel<<<grid, 256>>>(qkv, batch_ix, attn);
    }
    // 3) out projection + residual: res = attn @ w_out^T + b_out + slots
    {
        dim3 grid(D_MODEL / GBN, N_TOK / GBM);
        gemm_tf32_kernel<<<grid, 256>>>(attn, w_out, b_out, slots, res,
                                        N_TOK, D_MODEL, D_MODEL);
    }
    // 4) LayerNorm
    ln_kernel<<<N_TOK / 8, 256>>>(res, ln_gamma, ln_beta, out);
}

// round 3
// speedup vs baseline: 3.9770x; 2.7614x over previous
#include <cuda_runtime.h>
#include <math.h>
#include <stdint.h>

#define N_TOK 4096
#define D_MODEL 256
#define H_HEADS 8
#define HD 32
#define QKV_W 768

// ---------------- scratch (device globals; no allocation allowed) ----------
__device__ float g_qkv[N_TOK * QKV_W];    // [N, 3D]  (q | k | v)
__device__ float g_attn[N_TOK * D_MODEL]; // attention output
__device__ float g_res[N_TOK * D_MODEL];  // out-proj + residual (pre-LN)

// =================== mma / cp.async helpers ================================
__device__ __forceinline__ void mma_tf32(float& d0, float& d1, float& d2, float& d3,
                                         uint32_t a0, uint32_t a1, uint32_t a2, uint32_t a3,
                                         uint32_t b0, uint32_t b1) {
    asm volatile("mma.sync.aligned.m16n8k8.row.col.f32.tf32.tf32.f32 "
                 "{%0,%1,%2,%3}, {%4,%5,%6,%7}, {%8,%9}, {%0,%1,%2,%3};"
                 : "+f"(d0), "+f"(d1), "+f"(d2), "+f"(d3)
                 : "r"(a0), "r"(a1), "r"(a2), "r"(a3), "r"(b0), "r"(b1));
}

__device__ __forceinline__ void cp_async16(uint32_t dst, const void* src) {
    asm volatile("cp.async.cg.shared.global [%0], [%1], 16;" :: "r"(dst), "l"(src));
}
__device__ __forceinline__ void cp_commit() {
    asm volatile("cp.async.commit_group;");
}
template <int Nwait>
__device__ __forceinline__ void cp_wait() {
    asm volatile("cp.async.wait_group %0;" :: "n"(Nwait));
}

// =================== tf32 GEMM: C[M,N] = A[M,K] @ B[N,K]^T + bias (+resid) ==
// Block tile 128x64, 8 warps (4x2), warp tile 32x32, BK=32,
// cp.async double-buffered (prefetch depth 2). Raw fp32 bits fed to HMMA.TF32
// (hardware reads upper 19 bits => truncation; well within error budget).
#define GBM 128
#define GBN 64
#define GBK 32
#define GST 36   // smem row stride (floats): frag gathers land on banks 4g+tq

__global__ void gemm_tf32_kernel(const float* __restrict__ A,
                                 const float* __restrict__ B,
                                 const float* __restrict__ bias,
                                 const float* __restrict__ resid,
                                 float* __restrict__ C,
                                 int M, int N, int K) {
    extern __shared__ float sm[];
    float* As = sm;                       // [2][GBM][GST]
    float* Bs = sm + 2 * GBM * GST;       // [2][GBN][GST]

    const int t = threadIdx.x;            // 256 threads
    const int wid = t >> 5;
    const int lane = t & 31;
    const int g = lane >> 2;
    const int tq = lane & 3;
    const int wm = (wid & 3) * 32;
    const int wn = (wid >> 2) * 32;
    const int m0 = blockIdx.y * GBM;
    const int n0 = blockIdx.x * GBN;

    float acc[2][4][4];
#pragma unroll
    for (int mi = 0; mi < 2; mi++)
#pragma unroll
        for (int ni = 0; ni < 4; ni++)
#pragma unroll
            for (int c = 0; c < 4; c++) acc[mi][ni][c] = 0.f;

    const int T = K / GBK;

    auto issue = [&](int kt, int buf) {
        const float* Ab = A + (size_t)m0 * K + kt * GBK;
#pragma unroll
        for (int i = 0; i < 4; i++) {
            int fi = t + i * 256;
            int row = fi >> 3, c4 = fi & 7;
            cp_async16((uint32_t)__cvta_generic_to_shared(&As[(buf * GBM + row) * GST + c4 * 4]),
                       Ab + (size_t)row * K + c4 * 4);
        }
        const float* Bb = B + (size_t)n0 * K + kt * GBK;
#pragma unroll
        for (int i = 0; i < 2; i++) {
            int fi = t + i * 256;
            int row = fi >> 3, c4 = fi & 7;
            cp_async16((uint32_t)__cvta_generic_to_shared(&Bs[(buf * GBN + row) * GST + c4 * 4]),
                       Bb + (size_t)row * K + c4 * 4);
        }
        cp_commit();
    };

    issue(0, 0);
    if (T > 1) issue(1, 1);

    for (int i = 0; i < T; i++) {
        if (i + 1 < T) cp_wait<1>(); else cp_wait<0>();
        __syncthreads();

        const float* Ab = As + (i & 1) * GBM * GST;
        const float* Bb = Bs + (i & 1) * GBN * GST;
#pragma unroll
        for (int ks = 0; ks < GBK / 8; ks++) {
            const int kb = ks * 8;
            uint32_t a[2][4];
#pragma unroll
            for (int mi = 0; mi < 2; mi++) {
                int r0 = wm + mi * 16 + g;
                a[mi][0] = __float_as_uint(Ab[r0 * GST + kb + tq]);
                a[mi][1] = __float_as_uint(Ab[(r0 + 8) * GST + kb + tq]);
                a[mi][2] = __float_as_uint(Ab[r0 * GST + kb + tq + 4]);
                a[mi][3] = __float_as_uint(Ab[(r0 + 8) * GST + kb + tq + 4]);
            }
#pragma unroll
            for (int ni = 0; ni < 4; ni++) {
                int bc = wn + ni * 8 + g;
                uint32_t b0 = __float_as_uint(Bb[bc * GST + kb + tq]);
                uint32_t b1 = __float_as_uint(Bb[bc * GST + kb + tq + 4]);
#pragma unroll
                for (int mi = 0; mi < 2; mi++)
                    mma_tf32(acc[mi][ni][0], acc[mi][ni][1], acc[mi][ni][2], acc[mi][ni][3],
                             a[mi][0], a[mi][1], a[mi][2], a[mi][3], b0, b1);
            }
        }
        __syncthreads();
        if (i + 2 < T) issue(i + 2, i & 1);
    }

    // epilogue: bias (+resid)
#pragma unroll
    for (int mi = 0; mi < 2; mi++) {
#pragma unroll
        for (int ni = 0; ni < 4; ni++) {
            int col = n0 + wn + ni * 8 + 2 * tq;
            int r0 = m0 + wm + mi * 16 + g;
            int r1 = r0 + 8;
            float bx = bias[col], by = bias[col + 1];
            float2 v0 = make_float2(acc[mi][ni][0] + bx, acc[mi][ni][1] + by);
            float2 v1 = make_float2(acc[mi][ni][2] + bx, acc[mi][ni][3] + by);
            if (resid) {
                float2 rr0 = *(const float2*)&resid[(size_t)r0 * N + col];
                float2 rr1 = *(const float2*)&resid[(size_t)r1 * N + col];
                v0.x += rr0.x; v0.y += rr0.y;
                v1.x += rr1.x; v1.y += rr1.y;
            }
            *(float2*)&C[(size_t)r0 * N + col] = v0;
            *(float2*)&C[(size_t)r1 * N + col] = v1;
        }
    }
}

// ================= mma flash attention over block-diagonal mask =============
// batch_idx sorted -> contiguous segment per query tile. 128 threads (4 warps),
// warp w owns query rows [16w, 16w+16). tf32 m16n8k8 for S=QK^T and O+=P V.
#define QT 64
#define KT 64
#define KST 36   // Qs/Ks stride: frag banks 4g+tq (conflict-free)
#define VST 40   // Vs stride:    frag banks 8tq+g (conflict-free)
#define PST 68   // Ps stride:    frag banks 4g+tq (conflict-free)

__device__ __forceinline__ int lb_search(const int* __restrict__ a, int n, int v) {
    int lo = 0, hi = n;
    while (lo < hi) { int mid = (lo + hi) >> 1; if (a[mid] < v) lo = mid + 1; else hi = mid; }
    return lo;
}
__device__ __forceinline__ int ub_search(const int* __restrict__ a, int n, int v) {
    int lo = 0, hi = n;
    while (lo < hi) { int mid = (lo + hi) >> 1; if (a[mid] <= v) lo = mid + 1; else hi = mid; }
    return lo;
}

__global__ void flash_attn_kernel(const float* __restrict__ qkv,
                                  const int* __restrict__ bidx,
                                  float* __restrict__ attn_out) {
    __shared__ float Qs[QT * KST];
    __shared__ float Ks[KT * KST];
    __shared__ float Vs[KT * VST];
    __shared__ float Ps[QT * PST];
    __shared__ int qb[QT];
    __shared__ int kb[KT];

    const int h = blockIdx.y;
    const int q0 = blockIdx.x * QT;
    const int t = threadIdx.x;            // 128 threads
    const int wid = t >> 5;
    const int lane = t & 31;
    const int g = lane >> 2;
    const int tq = lane & 3;
    const int qoff = h * HD;
    const int koff = D_MODEL + h * HD;
    const int voff = 2 * D_MODEL + h * HD;

    // load Q tile (64 rows x 8 float4) + query batch ids
#pragma unroll
    for (int i = 0; i < 4; i++) {
        int fi = t + i * 128;
        int row = fi >> 3, c4 = fi & 7;
        *(float4*)&Qs[row * KST + c4 * 4] =
            *(const float4*)&qkv[(size_t)(q0 + row) * QKV_W + qoff + c4 * 4];
    }
    if (t < QT) qb[t] = bidx[q0 + t];
    __syncthreads();

    // Q fragments into registers (held for the whole block)
    uint32_t qf[4][4];
#pragma unroll
    for (int ks = 0; ks < 4; ks++) {
        int kbs = ks * 8;
        int r0 = wid * 16 + g;
        qf[ks][0] = __float_as_uint(Qs[r0 * KST + kbs + tq]);
        qf[ks][1] = __float_as_uint(Qs[(r0 + 8) * KST + kbs + tq]);
        qf[ks][2] = __float_as_uint(Qs[r0 * KST + kbs + tq + 4]);
        qf[ks][3] = __float_as_uint(Qs[(r0 + 8) * KST + kbs + tq + 4]);
    }
    const int myb0 = qb[wid * 16 + g];
    const int myb1 = qb[wid * 16 + g + 8];
    const int seg_s = lb_search(bidx, N_TOK, qb[0]);
    const int seg_e = ub_search(bidx, N_TOK, qb[QT - 1]);

    const float scale = 0.1767766952966369f; // 1/sqrt(32)
    // running max init 0: valid upper bound; makes exp(-1e30 - m) == 0 exactly
    float m0 = 0.f, m1 = 0.f, l0 = 0.f, l1 = 0.f;
    float oacc[4][4];
#pragma unroll
    for (int nt = 0; nt < 4; nt++)
#pragma unroll
        for (int c = 0; c < 4; c++) oacc[nt][c] = 0.f;

    for (int k0 = seg_s; k0 < seg_e; k0 += KT) {
        const int kt = min(KT, seg_e - k0);
        __syncthreads();
        // load K,V tiles (+ key batch ids), zero-fill tail
#pragma unroll
        for (int i = 0; i < 4; i++) {
            int fi = t + i * 128;
            int kk = fi >> 3, c4 = fi & 7;
            float4 kv = make_float4(0.f, 0.f, 0.f, 0.f);
            float4 vv = make_float4(0.f, 0.f, 0.f, 0.f);
            if (kk < kt) {
                size_t base = (size_t)(k0 + kk) * QKV_W;
                kv = *(const float4*)&qkv[base + koff + c4 * 4];
                vv = *(const float4*)&qkv[base + voff + c4 * 4];
            }
            *(float4*)&Ks[kk * KST + c4 * 4] = kv;
            *(float4*)&Vs[kk * VST + c4 * 4] = vv;
        }
        if (t < KT) kb[t] = (t < kt) ? bidx[k0 + t] : -1;
        __syncthreads();

        // ---- S = Q K^T (8 n-tiles x 4 k-steps of mma) ----
        float sacc[8][4];
#pragma unroll
        for (int nt = 0; nt < 8; nt++)
#pragma unroll
            for (int c = 0; c < 4; c++) sacc[nt][c] = 0.f;
#pragma unroll
        for (int ks = 0; ks < 4; ks++) {
            int kbs = ks * 8;
#pragma unroll
            for (int nt = 0; nt < 8; nt++) {
                int kr = nt * 8 + g;
                uint32_t b0 = __float_as_uint(Ks[kr * KST + kbs + tq]);
                uint32_t b1 = __float_as_uint(Ks[kr * KST + kbs + tq + 4]);
                mma_tf32(sacc[nt][0], sacc[nt][1], sacc[nt][2], sacc[nt][3],
                         qf[ks][0], qf[ks][1], qf[ks][2], qf[ks][3], b0, b1);
            }
        }

        // ---- mask + row max ----
        float rmax0 = -1e30f, rmax1 = -1e30f;
#pragma unroll
        for (int nt = 0; nt < 8; nt++) {
            int c0 = nt * 8 + 2 * tq;
            int kb0 = kb[c0], kb1 = kb[c0 + 1];
            float s0 = (kb0 == myb0) ? sacc[nt][0] * scale : -1e30f;
            float s1 = (kb1 == myb0) ? sacc[nt][1] * scale : -1e30f;
            float s2 = (kb0 == myb1) ? sacc[nt][2] * scale : -1e30f;
            float s3 = (kb1 == myb1) ? sacc[nt][3] * scale : -1e30f;
            sacc[nt][0] = s0; sacc[nt][1] = s1; sacc[nt][2] = s2; sacc[nt][3] = s3;
            rmax0 = fmaxf(rmax0, fmaxf(s0, s1));
            rmax1 = fmaxf(rmax1, fmaxf(s2, s3));
        }
        rmax0 = fmaxf(rmax0, __shfl_xor_sync(0xffffffffu, rmax0, 1));
        rmax0 = fmaxf(rmax0, __shfl_xor_sync(0xffffffffu, rmax0, 2));
        rmax1 = fmaxf(rmax1, __shfl_xor_sync(0xffffffffu, rmax1, 1));
        rmax1 = fmaxf(rmax1, __shfl_xor_sync(0xffffffffu, rmax1, 2));
        const float mn0 = fmaxf(m0, rmax0);
        const float mn1 = fmaxf(m1, rmax1);
        const float al0 = __expf(m0 - mn0);
        const float al1 = __expf(m1 - mn1);
        m0 = mn0; m1 = mn1;

        // ---- exp, write P tile (own rows only), update l ----
        float ls0 = 0.f, ls1 = 0.f;
        const int pr0 = (wid * 16 + g) * PST;
        const int pr1 = (wid * 16 + g + 8) * PST;
#pragma unroll
        for (int nt = 0; nt < 8; nt++) {
            float p0 = __expf(sacc[nt][0] - mn0);
            float p1 = __expf(sacc[nt][1] - mn0);
            float p2 = __expf(sacc[nt][2] - mn1);
            float p3 = __expf(sacc[nt][3] - mn1);
            ls0 += p0 + p1;
            ls1 += p2 + p3;
            *(float2*)&Ps[pr0 + nt * 8 + 2 * tq] = make_float2(p0, p1);
            *(float2*)&Ps[pr1 + nt * 8 + 2 * tq] = make_float2(p2, p3);
        }
        ls0 += __shfl_xor_sync(0xffffffffu, ls0, 1);
        ls0 += __shfl_xor_sync(0xffffffffu, ls0, 2);
        ls1 += __shfl_xor_sync(0xffffffffu, ls1, 1);
        ls1 += __shfl_xor_sync(0xffffffffu, ls1, 2);
        l0 = l0 * al0 + ls0;
        l1 = l1 * al1 + ls1;
#pragma unroll
        for (int nt = 0; nt < 4; nt++) {
            oacc[nt][0] *= al0; oacc[nt][1] *= al0;
            oacc[nt][2] *= al1; oacc[nt][3] *= al1;
        }
        __syncwarp();  // warp-local Ps rows visible across lanes

        // ---- O += P V (8 k-steps x 4 n-tiles of mma) ----
#pragma unroll
        for (int ks = 0; ks < 8; ks++) {
            int kk = ks * 8;
            uint32_t a0 = __float_as_uint(Ps[pr0 + kk + tq]);
            uint32_t a1 = __float_as_uint(Ps[pr1 + kk + tq]);
            uint32_t a2 = __float_as_uint(Ps[pr0 + kk + tq + 4]);
            uint32_t a3 = __float_as_uint(Ps[pr1 + kk + tq + 4]);
#pragma unroll
            for (int nt = 0; nt < 4; nt++) {
                uint32_t b0 = __float_as_uint(Vs[(kk + tq) * VST + nt * 8 + g]);
                uint32_t b1 = __float_as_uint(Vs[(kk + tq + 4) * VST + nt * 8 + g]);
                mma_tf32(oacc[nt][0], oacc[nt][1], oacc[nt][2], oacc[nt][3],
                         a0, a1, a2, a3, b0, b1);
            }
        }
    }

    const float i0 = 1.f / l0;
    const float i1 = 1.f / l1;
    const int r0 = q0 + wid * 16 + g;
    const int r1 = r0 + 8;
#pragma unroll
    for (int nt = 0; nt < 4; nt++) {
        int col = h * HD + nt * 8 + 2 * tq;
        *(float2*)&attn_out[(size_t)r0 * D_MODEL + col] =
            make_float2(oacc[nt][0] * i0, oacc[nt][1] * i0);
        *(float2*)&attn_out[(size_t)r1 * D_MODEL + col] =
            make_float2(oacc[nt][2] * i1, oacc[nt][3] * i1);
    }
}

// ================= LayerNorm (residual already folded in) ===================
__global__ void ln_kernel(const float* __restrict__ res,
                          const float* __restrict__ gamma,
                          const float* __restrict__ beta,
                          float* __restrict__ out) {
    const int w = threadIdx.x >> 5;
    const int lane = threadIdx.x & 31;
    const int row = blockIdx.x * 8 + w;

    const float4* p = (const float4*)&res[(size_t)row * D_MODEL];
    float4 v0 = p[lane];
    float4 v1 = p[lane + 32];

    float s = v0.x + v0.y + v0.z + v0.w + v1.x + v1.y + v1.z + v1.w;
#pragma unroll
    for (int o = 16; o > 0; o >>= 1) s += __shfl_xor_sync(0xffffffffu, s, o);
    const float mean = s * (1.f / D_MODEL);

    float d0x = v0.x - mean, d0y = v0.y - mean, d0z = v0.z - mean, d0w = v0.w - mean;
    float d1x = v1.x - mean, d1y = v1.y - mean, d1z = v1.z - mean, d1w = v1.w - mean;
    float sq = d0x * d0x + d0y * d0y + d0z * d0z + d0w * d0w
             + d1x * d1x + d1y * d1y + d1z * d1z + d1w * d1w;
#pragma unroll
    for (int o = 16; o > 0; o >>= 1) sq += __shfl_xor_sync(0xffffffffu, sq, o);
    const float rsig = rsqrtf(sq * (1.f / D_MODEL) + 1e-5f);

    const float4* gp = (const float4*)gamma;
    const float4* bp = (const float4*)beta;
    float4 g0 = gp[lane], g1 = gp[lane + 32];
    float4 b0 = bp[lane], b1 = bp[lane + 32];

    float4* op = (float4*)&out[(size_t)row * D_MODEL];
    op[lane] = make_float4(d0x * rsig * g0.x + b0.x, d0y * rsig * g0.y + b0.y,
                           d0z * rsig * g0.z + b0.z, d0w * rsig * g0.w + b0.w);
    op[lane + 32] = make_float4(d1x * rsig * g1.x + b1.x, d1y * rsig * g1.y + b1.y,
                                d1z * rsig * g1.z + b1.z, d1w * rsig * g1.w + b1.w);
}

// ---------------- launch ----------------------------------------------------
extern "C" void kernel_launch(void* const* d_in, const int* in_sizes, int n_in,
                              void* d_out, int out_size) {
    const float* slots    = (const float*)d_in[0];  // [1, N, D]
    const int*   batch_ix = (const int*)d_in[1];    // [N]
    const float* w_in     = (const float*)d_in[2];  // [3D, D]
    const float* b_in     = (const float*)d_in[3];  // [3D]
    const float* w_out    = (const float*)d_in[4];  // [D, D]
    const float* b_out    = (const float*)d_in[5];  // [D]
    const float* ln_gamma = (const float*)d_in[6];  // [D]
    const float* ln_beta  = (const float*)d_in[7];  // [D]
    float* out = (float*)d_out;

    float* qkv;  cudaGetSymbolAddress((void**)&qkv,  g_qkv);
    float* attn; cudaGetSymbolAddress((void**)&attn, g_attn);
    float* res;  cudaGetSymbolAddress((void**)&res,  g_res);

    const int gemm_smem = (2 * GBM * GST + 2 * GBN * GST) * (int)sizeof(float); // 55296
    cudaFuncSetAttribute(gemm_tf32_kernel,
                         cudaFuncAttributeMaxDynamicSharedMemorySize, gemm_smem);

    // 1) QKV projection: qkv[N, 768] = slots @ w_in^T + b_in
    {
        dim3 grid(QKV_W / GBN, N_TOK / GBM);
        gemm_tf32_kernel<<<grid, 256, gemm_smem>>>(slots, w_in, b_in, nullptr, qkv,
                                                   N_TOK, QKV_W, D_MODEL);
    }
    // 2) block-diagonal flash attention (tf32 mma)
    {
        dim3 grid(N_TOK / QT, H_HEADS);
        flash_attn_kernel<<<grid, 128>>>(qkv, batch_ix, attn);
    }
    // 3) out projection + residual: res = attn @ w_out^T + b_out + slots
    {
        dim3 grid(D_MODEL / GBN, N_TOK / GBM);
        gemm_tf32_kernel<<<grid, 256, gemm_smem>>>(attn, w_out, b_out, slots, res,
                                                   N_TOK, D_MODEL, D_MODEL);
    }
    // 4) LayerNorm
    ln_kernel<<<N_TOK / 8, 256>>>(res, ln_gamma, ln_beta, out);
}

// round 4
// speedup vs baseline: 4.3996x; 1.1063x over previous
#include <cuda_runtime.h>
#include <cuda_bf16.h>
#include <math.h>
#include <stdint.h>

#define N_TOK 4096
#define D_MODEL 256
#define H_HEADS 8
#define HD 32
#define QKV_W 768

// ---------------- scratch (device globals; no allocation allowed) ----------
__device__ float g_qkv[N_TOK * QKV_W];                     // fp32 q|k|v
__device__ __nv_bfloat16 g_attn_bf[N_TOK * D_MODEL];       // attention out (bf16)
__device__ __nv_bfloat16 g_slots_bf[N_TOK * D_MODEL];
__device__ __nv_bfloat16 g_win_bf[QKV_W * D_MODEL];
__device__ __nv_bfloat16 g_wout_bf[D_MODEL * D_MODEL];

// =================== mma / cp.async helpers ================================
__device__ __forceinline__ void mma_tf32(float& d0, float& d1, float& d2, float& d3,
                                         uint32_t a0, uint32_t a1, uint32_t a2, uint32_t a3,
                                         uint32_t b0, uint32_t b1) {
    asm volatile("mma.sync.aligned.m16n8k8.row.col.f32.tf32.tf32.f32 "
                 "{%0,%1,%2,%3}, {%4,%5,%6,%7}, {%8,%9}, {%0,%1,%2,%3};"
                 : "+f"(d0), "+f"(d1), "+f"(d2), "+f"(d3)
                 : "r"(a0), "r"(a1), "r"(a2), "r"(a3), "r"(b0), "r"(b1));
}

__device__ __forceinline__ void mma_bf16(float& d0, float& d1, float& d2, float& d3,
                                         uint32_t a0, uint32_t a1, uint32_t a2, uint32_t a3,
                                         uint32_t b0, uint32_t b1) {
    asm volatile("mma.sync.aligned.m16n8k16.row.col.f32.bf16.bf16.f32 "
                 "{%0,%1,%2,%3}, {%4,%5,%6,%7}, {%8,%9}, {%0,%1,%2,%3};"
                 : "+f"(d0), "+f"(d1), "+f"(d2), "+f"(d3)
                 : "r"(a0), "r"(a1), "r"(a2), "r"(a3), "r"(b0), "r"(b1));
}

__device__ __forceinline__ void cp_async16(uint32_t dst, const void* src) {
    asm volatile("cp.async.cg.shared.global [%0], [%1], 16;" :: "r"(dst), "l"(src));
}
__device__ __forceinline__ void cp_commit() {
    asm volatile("cp.async.commit_group;");
}
template <int Nwait>
__device__ __forceinline__ void cp_wait() {
    asm volatile("cp.async.wait_group %0;" :: "n"(Nwait));
}

// =================== fp32 -> bf16 conversion (3 arrays, one launch) ========
__global__ void cvt_bf16_kernel(const float* __restrict__ s0, __nv_bfloat16* __restrict__ d0, int n0,
                                const float* __restrict__ s1, __nv_bfloat16* __restrict__ d1, int n1,
                                const float* __restrict__ s2, __nv_bfloat16* __restrict__ d2, int n2) {
    int i = blockIdx.x * blockDim.x + threadIdx.x;  // one float4 per thread
    const float* s;
    __nv_bfloat16* d;
    int off;
    int q0 = n0 >> 2, q1 = q0 + (n1 >> 2), q2 = q1 + (n2 >> 2);
    if (i >= q2) return;
    if (i < q0) { s = s0; d = d0; off = i * 4; }
    else if (i < q1) { s = s1; d = d1; off = (i - q0) * 4; }
    else { s = s2; d = d2; off = (i - q1) * 4; }
    float4 v = *(const float4*)&s[off];
    __nv_bfloat162 lo = __float22bfloat162_rn(make_float2(v.x, v.y));
    __nv_bfloat162 hi = __float22bfloat162_rn(make_float2(v.z, v.w));
    *(__nv_bfloat162*)&d[off] = lo;
    *(__nv_bfloat162*)&d[off + 2] = hi;
}

// =================== bf16 GEMM: C[M,N] = A[M,K] @ B[N,K]^T + bias ==========
// Block tile 128x64, 8 warps (4x2), warp tile 32x32, BK=32 bf16, m16n8k16,
// cp.async double-buffered. Smem row stride 20 words (40 bf16): fragment
// gathers (20g+tq mod 32) hit 32 distinct banks.
#define GBM 128
#define GBN 64
#define GBK 32
#define GSTW 20

__global__ void gemm_bf16_kernel(const __nv_bfloat16* __restrict__ A,
                                 const __nv_bfloat16* __restrict__ B,
                                 const float* __restrict__ bias,
                                 float* __restrict__ C,
                                 int M, int N, int K) {
    __shared__ uint32_t As[2 * GBM * GSTW];
    __shared__ uint32_t Bs[2 * GBN * GSTW];

    const int t = threadIdx.x;            // 256 threads
    const int wid = t >> 5;
    const int lane = t & 31;
    const int g = lane >> 2;
    const int tq = lane & 3;
    const int wm = (wid & 3) * 32;
    const int wn = (wid >> 2) * 32;
    const int m0 = blockIdx.y * GBM;
    const int n0 = blockIdx.x * GBN;

    float acc[2][4][4];
#pragma unroll
    for (int mi = 0; mi < 2; mi++)
#pragma unroll
        for (int ni = 0; ni < 4; ni++)
#pragma unroll
            for (int c = 0; c < 4; c++) acc[mi][ni][c] = 0.f;

    const int T = K / GBK;

    auto issue = [&](int kt, int buf) {
        const __nv_bfloat16* Ab = A + (size_t)m0 * K + kt * GBK;
#pragma unroll
        for (int i = 0; i < 2; i++) {
            int fi = t + i * 256;                // 512 chunks: 128 rows x 4
            int row = fi >> 2, c16 = fi & 3;
            cp_async16((uint32_t)__cvta_generic_to_shared(&As[(buf * GBM + row) * GSTW + c16 * 4]),
                       Ab + (size_t)row * K + c16 * 8);
        }
        const __nv_bfloat16* Bb = B + (size_t)n0 * K + kt * GBK;
        {
            int row = t >> 2, c16 = t & 3;      // 256 chunks: 64 rows x 4
            cp_async16((uint32_t)__cvta_generic_to_shared(&Bs[(buf * GBN + row) * GSTW + c16 * 4]),
                       Bb + (size_t)row * K + c16 * 8);
        }
        cp_commit();
    };

    issue(0, 0);
    if (T > 1) issue(1, 1);

    for (int i = 0; i < T; i++) {
        if (i + 1 < T) cp_wait<1>(); else cp_wait<0>();
        __syncthreads();

        const uint32_t* Ab = As + (i & 1) * GBM * GSTW;
        const uint32_t* Bb = Bs + (i & 1) * GBN * GSTW;
#pragma unroll
        for (int ks = 0; ks < 2; ks++) {       // two k16 steps per BK=32
            const int kw = ks * 8;
            uint32_t a[2][4];
#pragma unroll
            for (int mi = 0; mi < 2; mi++) {
                int r0 = wm + mi * 16 + g;
                a[mi][0] = Ab[r0 * GSTW + kw + tq];
                a[mi][1] = Ab[(r0 + 8) * GSTW + kw + tq];
                a[mi][2] = Ab[r0 * GSTW + kw + tq + 4];
                a[mi][3] = Ab[(r0 + 8) * GSTW + kw + tq + 4];
            }
#pragma unroll
            for (int ni = 0; ni < 4; ni++) {
                int bc = wn + ni * 8 + g;
                uint32_t b0 = Bb[bc * GSTW + kw + tq];
                uint32_t b1 = Bb[bc * GSTW + kw + tq + 4];
#pragma unroll
                for (int mi = 0; mi < 2; mi++)
                    mma_bf16(acc[mi][ni][0], acc[mi][ni][1], acc[mi][ni][2], acc[mi][ni][3],
                             a[mi][0], a[mi][1], a[mi][2], a[mi][3], b0, b1);
            }
        }
        __syncthreads();
        if (i + 2 < T) issue(i + 2, i & 1);
    }

#pragma unroll
    for (int mi = 0; mi < 2; mi++) {
#pragma unroll
        for (int ni = 0; ni < 4; ni++) {
            int col = n0 + wn + ni * 8 + 2 * tq;
            int r0 = m0 + wm + mi * 16 + g;
            int r1 = r0 + 8;
            float bx = bias[col], by = bias[col + 1];
            *(float2*)&C[(size_t)r0 * N + col] = make_float2(acc[mi][ni][0] + bx, acc[mi][ni][1] + by);
            *(float2*)&C[(size_t)r1 * N + col] = make_float2(acc[mi][ni][2] + bx, acc[mi][ni][3] + by);
        }
    }
}

// ====== fused GEMM2 + bias + residual + LayerNorm ===========================
// out = LN(resid + A @ B^T + bias). Block tile 32x256 (full rows), 8 warps
// (2m x 4n), warp tile 16x64. A,B bf16; K=N=256 fixed.
#define G2BM 32
#define G2BN 256

__global__ void gemm2_ln_kernel(const __nv_bfloat16* __restrict__ A,
                                const __nv_bfloat16* __restrict__ B,
                                const float* __restrict__ bias,
                                const float* __restrict__ resid,
                                const float* __restrict__ gamma,
                                const float* __restrict__ beta,
                                float* __restrict__ out) {
    __shared__ uint32_t sm[2 * G2BM * GSTW + 2 * G2BN * GSTW];  // 11520 words
    uint32_t* As = sm;
    uint32_t* Bs = sm + 2 * G2BM * GSTW;
    float* Cs = (float*)sm;                 // epilogue alias, stride 264

    const int t = threadIdx.x;              // 256 threads
    const int wid = t >> 5;
    const int lane = t & 31;
    const int g = lane >> 2;
    const int tq = lane & 3;
    const int wm = (wid & 1) * 16;
    const int wn = (wid >> 1) * 64;
    const int m0 = blockIdx.x * G2BM;
    const int K = 256, T = 8;

    float acc[8][4];
#pragma unroll
    for (int ni = 0; ni < 8; ni++)
#pragma unroll
        for (int c = 0; c < 4; c++) acc[ni][c] = 0.f;

    auto issue = [&](int kt, int buf) {
        if (t < 128) {                      // A: 32 rows x 4 chunks
            int row = t >> 2, c16 = t & 3;
            cp_async16((uint32_t)__cvta_generic_to_shared(&As[(buf * G2BM + row) * GSTW + c16 * 4]),
                       A + (size_t)(m0 + row) * K + kt * GBK + c16 * 8);
        }
#pragma unroll
        for (int i = 0; i < 4; i++) {       // B: 256 rows x 4 chunks
            int fi = t + i * 256;
            int row = fi >> 2, c16 = fi & 3;
            cp_async16((uint32_t)__cvta_generic_to_shared(&Bs[(buf * G2BN + row) * GSTW + c16 * 4]),
                       B + (size_t)row * K + kt * GBK + c16 * 8);
        }
        cp_commit();
    };

    issue(0, 0);
    issue(1, 1);

    for (int i = 0; i < T; i++) {
        if (i + 1 < T) cp_wait<1>(); else cp_wait<0>();
        __syncthreads();

        const uint32_t* Ab = As + (i & 1) * G2BM * GSTW;
        const uint32_t* Bb = Bs + (i & 1) * G2BN * GSTW;
#pragma unroll
        for (int ks = 0; ks < 2; ks++) {
            const int kw = ks * 8;
            int r0 = wm + g;
            uint32_t a0 = Ab[r0 * GSTW + kw + tq];
            uint32_t a1 = Ab[(r0 + 8) * GSTW + kw + tq];
            uint32_t a2 = Ab[r0 * GSTW + kw + tq + 4];
            uint32_t a3 = Ab[(r0 + 8) * GSTW + kw + tq + 4];
#pragma unroll
            for (int ni = 0; ni < 8; ni++) {
                int bc = wn + ni * 8 + g;
                uint32_t b0 = Bb[bc * GSTW + kw + tq];
                uint32_t b1 = Bb[bc * GSTW + kw + tq + 4];
                mma_bf16(acc[ni][0], acc[ni][1], acc[ni][2], acc[ni][3],
                         a0, a1, a2, a3, b0, b1);
            }
        }
        __syncthreads();
        if (i + 2 < T) issue(i + 2, i & 1);
    }

    // stage acc + bias into smem rows (delta tile, full 256-wide rows)
    const int r0 = wm + g;
#pragma unroll
    for (int ni = 0; ni < 8; ni++) {
        int col = wn + ni * 8 + 2 * tq;
        float bx = bias[col], by = bias[col + 1];
        *(float2*)&Cs[r0 * 264 + col] = make_float2(acc[ni][0] + bx, acc[ni][1] + by);
        *(float2*)&Cs[(r0 + 8) * 264 + col] = make_float2(acc[ni][2] + bx, acc[ni][3] + by);
    }
    __syncthreads();

    // LayerNorm over 32 rows: warp w handles rows w, w+8, w+16, w+24
    for (int rr = wid; rr < G2BM; rr += 8) {
        const int grow = m0 + rr;
        float v[8], s = 0.f;
#pragma unroll
        for (int k = 0; k < 8; k++) {
            int c = lane + 32 * k;
            v[k] = Cs[rr * 264 + c] + resid[(size_t)grow * 256 + c];
            s += v[k];
        }
#pragma unroll
        for (int o = 16; o > 0; o >>= 1) s += __shfl_xor_sync(0xffffffffu, s, o);
        const float mean = s * (1.f / 256.f);
        float sq = 0.f;
#pragma unroll
        for (int k = 0; k < 8; k++) { float d = v[k] - mean; sq += d * d; }
#pragma unroll
        for (int o = 16; o > 0; o >>= 1) sq += __shfl_xor_sync(0xffffffffu, sq, o);
        const float rsig = rsqrtf(sq * (1.f / 256.f) + 1e-5f);
#pragma unroll
        for (int k = 0; k < 8; k++) {
            int c = lane + 32 * k;
            out[(size_t)grow * 256 + c] = (v[k] - mean) * rsig * gamma[c] + beta[c];
        }
    }
}

// ================= mma flash attention over block-diagonal mask =============
#define QT 64
#define KT 64
#define KST 36
#define VST 40
#define PST 68

__device__ __forceinline__ int lb_search(const int* __restrict__ a, int n, int v) {
    int lo = 0, hi = n;
    while (lo < hi) { int mid = (lo + hi) >> 1; if (a[mid] < v) lo = mid + 1; else hi = mid; }
    return lo;
}
__device__ __forceinline__ int ub_search(const int* __restrict__ a, int n, int v) {
    int lo = 0, hi = n;
    while (lo < hi) { int mid = (lo + hi) >> 1; if (a[mid] <= v) lo = mid + 1; else hi = mid; }
    return lo;
}

__global__ void flash_attn_kernel(const float* __restrict__ qkv,
                                  const int* __restrict__ bidx,
                                  __nv_bfloat16* __restrict__ attn_out) {
    __shared__ float Qs[QT * KST];
    __shared__ float Ks[KT * KST];
    __shared__ float Vs[KT * VST];
    __shared__ float Ps[QT * PST];
    __shared__ int qb[QT];
    __shared__ int kb[KT];

    const int h = blockIdx.y;
    const int q0 = blockIdx.x * QT;
    const int t = threadIdx.x;            // 128 threads
    const int wid = t >> 5;
    const int lane = t & 31;
    const int g = lane >> 2;
    const int tq = lane & 3;
    const int qoff = h * HD;
    const int koff = D_MODEL + h * HD;
    const int voff = 2 * D_MODEL + h * HD;

#pragma unroll
    for (int i = 0; i < 4; i++) {
        int fi = t + i * 128;
        int row = fi >> 3, c4 = fi & 7;
        *(float4*)&Qs[row * KST + c4 * 4] =
            *(const float4*)&qkv[(size_t)(q0 + row) * QKV_W + qoff + c4 * 4];
    }
    if (t < QT) qb[t] = bidx[q0 + t];
    __syncthreads();

    uint32_t qf[4][4];
#pragma unroll
    for (int ks = 0; ks < 4; ks++) {
        int kbs = ks * 8;
        int r0 = wid * 16 + g;
        qf[ks][0] = __float_as_uint(Qs[r0 * KST + kbs + tq]);
        qf[ks][1] = __float_as_uint(Qs[(r0 + 8) * KST + kbs + tq]);
        qf[ks][2] = __float_as_uint(Qs[r0 * KST + kbs + tq + 4]);
        qf[ks][3] = __float_as_uint(Qs[(r0 + 8) * KST + kbs + tq + 4]);
    }
    const int myb0 = qb[wid * 16 + g];
    const int myb1 = qb[wid * 16 + g + 8];
    const int seg_s = lb_search(bidx, N_TOK, qb[0]);
    const int seg_e = ub_search(bidx, N_TOK, qb[QT - 1]);

    const float scale = 0.1767766952966369f;
    float m0 = 0.f, m1 = 0.f, l0 = 0.f, l1 = 0.f;
    float oacc[4][4];
#pragma unroll
    for (int nt = 0; nt < 4; nt++)
#pragma unroll
        for (int c = 0; c < 4; c++) oacc[nt][c] = 0.f;

    for (int k0 = seg_s; k0 < seg_e; k0 += KT) {
        const int kt = min(KT, seg_e - k0);
        __syncthreads();
#pragma unroll
        for (int i = 0; i < 4; i++) {
            int fi = t + i * 128;
            int kk = fi >> 3, c4 = fi & 7;
            float4 kv = make_float4(0.f, 0.f, 0.f, 0.f);
            float4 vv = make_float4(0.f, 0.f, 0.f, 0.f);
            if (kk < kt) {
                size_t base = (size_t)(k0 + kk) * QKV_W;
                kv = *(const float4*)&qkv[base + koff + c4 * 4];
                vv = *(const float4*)&qkv[base + voff + c4 * 4];
            }
            *(float4*)&Ks[kk * KST + c4 * 4] = kv;
            *(float4*)&Vs[kk * VST + c4 * 4] = vv;
        }
        if (t < KT) kb[t] = (t < kt) ? bidx[k0 + t] : -1;
        __syncthreads();

        float sacc[8][4];
#pragma unroll
        for (int nt = 0; nt < 8; nt++)
#pragma unroll
            for (int c = 0; c < 4; c++) sacc[nt][c] = 0.f;
#pragma unroll
        for (int ks = 0; ks < 4; ks++) {
            int kbs = ks * 8;
#pragma unroll
            for (int nt = 0; nt < 8; nt++) {
                int kr = nt * 8 + g;
                uint32_t b0 = __float_as_uint(Ks[kr * KST + kbs + tq]);
                uint32_t b1 = __float_as_uint(Ks[kr * KST + kbs + tq + 4]);
                mma_tf32(sacc[nt][0], sacc[nt][1], sacc[nt][2], sacc[nt][3],
                         qf[ks][0], qf[ks][1], qf[ks][2], qf[ks][3], b0, b1);
            }
        }

        float rmax0 = -1e30f, rmax1 = -1e30f;
#pragma unroll
        for (int nt = 0; nt < 8; nt++) {
            int c0 = nt * 8 + 2 * tq;
            int kb0 = kb[c0], kb1 = kb[c0 + 1];
            float s0 = (kb0 == myb0) ? sacc[nt][0] * scale : -1e30f;
            float s1 = (kb1 == myb0) ? sacc[nt][1] * scale : -1e30f;
            float s2 = (kb0 == myb1) ? sacc[nt][2] * scale : -1e30f;
            float s3 = (kb1 == myb1) ? sacc[nt][3] * scale : -1e30f;
            sacc[nt][0] = s0; sacc[nt][1] = s1; sacc[nt][2] = s2; sacc[nt][3] = s3;
            rmax0 = fmaxf(rmax0, fmaxf(s0, s1));
            rmax1 = fmaxf(rmax1, fmaxf(s2, s3));
        }
        rmax0 = fmaxf(rmax0, __shfl_xor_sync(0xffffffffu, rmax0, 1));
        rmax0 = fmaxf(rmax0, __shfl_xor_sync(0xffffffffu, rmax0, 2));
        rmax1 = fmaxf(rmax1, __shfl_xor_sync(0xffffffffu, rmax1, 1));
        rmax1 = fmaxf(rmax1, __shfl_xor_sync(0xffffffffu, rmax1, 2));
        const float mn0 = fmaxf(m0, rmax0);
        const float mn1 = fmaxf(m1, rmax1);
        const float al0 = __expf(m0 - mn0);
        const float al1 = __expf(m1 - mn1);
        m0 = mn0; m1 = mn1;

        float ls0 = 0.f, ls1 = 0.f;
        const int pr0 = (wid * 16 + g) * PST;
        const int pr1 = (wid * 16 + g + 8) * PST;
#pragma unroll
        for (int nt = 0; nt < 8; nt++) {
            float p0 = __expf(sacc[nt][0] - mn0);
            float p1 = __expf(sacc[nt][1] - mn0);
            float p2 = __expf(sacc[nt][2] - mn1);
            float p3 = __expf(sacc[nt][3] - mn1);
            ls0 += p0 + p1;
            ls1 += p2 + p3;
            *(float2*)&Ps[pr0 + nt * 8 + 2 * tq] = make_float2(p0, p1);
            *(float2*)&Ps[pr1 + nt * 8 + 2 * tq] = make_float2(p2, p3);
        }
        ls0 += __shfl_xor_sync(0xffffffffu, ls0, 1);
        ls0 += __shfl_xor_sync(0xffffffffu, ls0, 2);
        ls1 += __shfl_xor_sync(0xffffffffu, ls1, 1);
        ls1 += __shfl_xor_sync(0xffffffffu, ls1, 2);
        l0 = l0 * al0 + ls0;
        l1 = l1 * al1 + ls1;
#pragma unroll
        for (int nt = 0; nt < 4; nt++) {
            oacc[nt][0] *= al0; oacc[nt][1] *= al0;
            oacc[nt][2] *= al1; oacc[nt][3] *= al1;
        }
        __syncwarp();

#pragma unroll
        for (int ks = 0; ks < 8; ks++) {
            int kk = ks * 8;
            uint32_t a0 = __float_as_uint(Ps[pr0 + kk + tq]);
            uint32_t a1 = __float_as_uint(Ps[pr1 + kk + tq]);
            uint32_t a2 = __float_as_uint(Ps[pr0 + kk + tq + 4]);
            uint32_t a3 = __float_as_uint(Ps[pr1 + kk + tq + 4]);
#pragma unroll
            for (int nt = 0; nt < 4; nt++) {
                uint32_t b0 = __float_as_uint(Vs[(kk + tq) * VST + nt * 8 + g]);
                uint32_t b1 = __float_as_uint(Vs[(kk + tq + 4) * VST + nt * 8 + g]);
                mma_tf32(oacc[nt][0], oacc[nt][1], oacc[nt][2], oacc[nt][3],
                         a0, a1, a2, a3, b0, b1);
            }
        }
    }

    const float i0 = 1.f / l0;
    const float i1 = 1.f / l1;
    const int r0 = q0 + wid * 16 + g;
    const int r1 = r0 + 8;
#pragma unroll
    for (int nt = 0; nt < 4; nt++) {
        int col = h * HD + nt * 8 + 2 * tq;
        *(__nv_bfloat162*)&attn_out[(size_t)r0 * D_MODEL + col] =
            __float22bfloat162_rn(make_float2(oacc[nt][0] * i0, oacc[nt][1] * i0));
        *(__nv_bfloat162*)&attn_out[(size_t)r1 * D_MODEL + col] =
            __float22bfloat162_rn(make_float2(oacc[nt][2] * i1, oacc[nt][3] * i1));
    }
}

// ---------------- launch ----------------------------------------------------
extern "C" void kernel_launch(void* const* d_in, const int* in_sizes, int n_in,
                              void* d_out, int out_size) {
    const float* slots    = (const float*)d_in[0];
    const int*   batch_ix = (const int*)d_in[1];
    const float* w_in     = (const float*)d_in[2];
    const float* b_in     = (const float*)d_in[3];
    const float* w_out    = (const float*)d_in[4];
    const float* b_out    = (const float*)d_in[5];
    const float* ln_gamma = (const float*)d_in[6];
    const float* ln_beta  = (const float*)d_in[7];
    float* out = (float*)d_out;

    float* qkv;              cudaGetSymbolAddress((void**)&qkv,      g_qkv);
    __nv_bfloat16* attn_bf;  cudaGetSymbolAddress((void**)&attn_bf,  g_attn_bf);
    __nv_bfloat16* slots_bf; cudaGetSymbolAddress((void**)&slots_bf, g_slots_bf);
    __nv_bfloat16* win_bf;   cudaGetSymbolAddress((void**)&win_bf,   g_win_bf);
    __nv_bfloat16* wout_bf;  cudaGetSymbolAddress((void**)&wout_bf,  g_wout_bf);

    // 0) convert inputs to bf16 (slots, w_in, w_out)
    {
        const int n0 = N_TOK * D_MODEL, n1 = QKV_W * D_MODEL, n2 = D_MODEL * D_MODEL;
        const int total4 = (n0 + n1 + n2) / 4;
        cvt_bf16_kernel<<<(total4 + 255) / 256, 256>>>(slots, slots_bf, n0,
                                                       w_in, win_bf, n1,
                                                       w_out, wout_bf, n2);
    }
    // 1) QKV projection: qkv[N, 768] = slots @ w_in^T + b_in  (bf16 mma, fp32 out)
    {
        dim3 grid(QKV_W / GBN, N_TOK / GBM);
        gemm_bf16_kernel<<<grid, 256>>>(slots_bf, win_bf, b_in, qkv,
                                        N_TOK, QKV_W, D_MODEL);
    }
    // 2) block-diagonal flash attention (tf32 mma), writes bf16
    {
        dim3 grid(N_TOK / QT, H_HEADS);
        flash_attn_kernel<<<grid, 128>>>(qkv, batch_ix, attn_bf);
    }
    // 3) fused out-projection + bias + residual + LayerNorm
    gemm2_ln_kernel<<<N_TOK / G2BM, 256>>>(attn_bf, wout_bf, b_out, slots,
                                           ln_gamma, ln_beta, out);
}

// round 6
// speedup vs baseline: 4.7548x; 1.0807x over previous
#include <cuda_runtime.h>
#include <cuda_bf16.h>
#include <math.h>
#include <stdint.h>

#define N_TOK 4096
#define D_MODEL 256
#define H_HEADS 8
#define HD 32
#define QKV_W 768

// ---------------- scratch (device globals; no allocation allowed) ----------
__device__ __nv_bfloat16 g_qkv_bf[N_TOK * QKV_W];      // bf16 q|k|v
__device__ __nv_bfloat16 g_attn_bf[N_TOK * D_MODEL];   // attention out (bf16)
__device__ __nv_bfloat16 g_slots_bf[N_TOK * D_MODEL];
__device__ __nv_bfloat16 g_win_bf[QKV_W * D_MODEL];
__device__ __nv_bfloat16 g_wout_bf[D_MODEL * D_MODEL];

// =================== mma / cp.async helpers ================================
__device__ __forceinline__ void mma_bf16(float& d0, float& d1, float& d2, float& d3,
                                         uint32_t a0, uint32_t a1, uint32_t a2, uint32_t a3,
                                         uint32_t b0, uint32_t b1) {
    asm volatile("mma.sync.aligned.m16n8k16.row.col.f32.bf16.bf16.f32 "
                 "{%0,%1,%2,%3}, {%4,%5,%6,%7}, {%8,%9}, {%0,%1,%2,%3};"
                 : "+f"(d0), "+f"(d1), "+f"(d2), "+f"(d3)
                 : "r"(a0), "r"(a1), "r"(a2), "r"(a3), "r"(b0), "r"(b1));
}

__device__ __forceinline__ void cp_async16(uint32_t dst, const void* src) {
    asm volatile("cp.async.cg.shared.global [%0], [%1], 16;" :: "r"(dst), "l"(src));
}
__device__ __forceinline__ void cp_commit() {
    asm volatile("cp.async.commit_group;");
}
template <int Nwait>
__device__ __forceinline__ void cp_wait() {
    asm volatile("cp.async.wait_group %0;" :: "n"(Nwait));
}

// pack two fp32 into one bf16x2 register (lo -> low half, hi -> high half)
__device__ __forceinline__ uint32_t pack_bf16x2(float lo, float hi) {
    uint32_t r;
    asm("cvt.rn.bf16x2.f32 %0, %1, %2;" : "=r"(r) : "f"(hi), "f"(lo));
    return r;
}

// =================== fp32 -> bf16 conversion (3 arrays, one launch) ========
__global__ void cvt_bf16_kernel(const float* __restrict__ s0, __nv_bfloat16* __restrict__ d0, int n0,
                                const float* __restrict__ s1, __nv_bfloat16* __restrict__ d1, int n1,
                                const float* __restrict__ s2, __nv_bfloat16* __restrict__ d2, int n2) {
    int i = blockIdx.x * blockDim.x + threadIdx.x;  // one float4 per thread
    const float* s;
    __nv_bfloat16* d;
    int off;
    int q0 = n0 >> 2, q1 = q0 + (n1 >> 2), q2 = q1 + (n2 >> 2);
    if (i >= q2) return;
    if (i < q0) { s = s0; d = d0; off = i * 4; }
    else if (i < q1) { s = s1; d = d1; off = (i - q0) * 4; }
    else { s = s2; d = d2; off = (i - q1) * 4; }
    float4 v = *(const float4*)&s[off];
    *(uint32_t*)&d[off] = pack_bf16x2(v.x, v.y);
    *(uint32_t*)&d[off + 2] = pack_bf16x2(v.z, v.w);
}

// ===== bf16 GEMM: C[M,N] = A[M,K] @ B[N,K]^T + bias, bf16 output ===========
// Block tile 128x64, 8 warps (4x2), warp tile 32x32, BK=32, m16n8k16,
// cp.async double-buffered. Smem row stride 20 words: conflict-free frags.
#define GBM 128
#define GBN 64
#define GBK 32
#define GSTW 20

__global__ void gemm_bf16_kernel(const __nv_bfloat16* __restrict__ A,
                                 const __nv_bfloat16* __restrict__ B,
                                 const float* __restrict__ bias,
                                 __nv_bfloat16* __restrict__ C,
                                 int M, int N, int K) {
    __shared__ uint32_t As[2 * GBM * GSTW];
    __shared__ uint32_t Bs[2 * GBN * GSTW];

    const int t = threadIdx.x;            // 256 threads
    const int wid = t >> 5;
    const int lane = t & 31;
    const int g = lane >> 2;
    const int tq = lane & 3;
    const int wm = (wid & 3) * 32;
    const int wn = (wid >> 2) * 32;
    const int m0 = blockIdx.y * GBM;
    const int n0 = blockIdx.x * GBN;

    float acc[2][4][4];
#pragma unroll
    for (int mi = 0; mi < 2; mi++)
#pragma unroll
        for (int ni = 0; ni < 4; ni++)
#pragma unroll
            for (int c = 0; c < 4; c++) acc[mi][ni][c] = 0.f;

    const int T = K / GBK;

    auto issue = [&](int kt, int buf) {
        const __nv_bfloat16* Ab = A + (size_t)m0 * K + kt * GBK;
#pragma unroll
        for (int i = 0; i < 2; i++) {
            int fi = t + i * 256;
            int row = fi >> 2, c16 = fi & 3;
            cp_async16((uint32_t)__cvta_generic_to_shared(&As[(buf * GBM + row) * GSTW + c16 * 4]),
                       Ab + (size_t)row * K + c16 * 8);
        }
        const __nv_bfloat16* Bb = B + (size_t)n0 * K + kt * GBK;
        {
            int row = t >> 2, c16 = t & 3;
            cp_async16((uint32_t)__cvta_generic_to_shared(&Bs[(buf * GBN + row) * GSTW + c16 * 4]),
                       Bb + (size_t)row * K + c16 * 8);
        }
        cp_commit();
    };

    issue(0, 0);
    if (T > 1) issue(1, 1);

    for (int i = 0; i < T; i++) {
        if (i + 1 < T) cp_wait<1>(); else cp_wait<0>();
        __syncthreads();

        const uint32_t* Ab = As + (i & 1) * GBM * GSTW;
        const uint32_t* Bb = Bs + (i & 1) * GBN * GSTW;
#pragma unroll
        for (int ks = 0; ks < 2; ks++) {
            const int kw = ks * 8;
            uint32_t a[2][4];
#pragma unroll
            for (int mi = 0; mi < 2; mi++) {
                int r0 = wm + mi * 16 + g;
                a[mi][0] = Ab[r0 * GSTW + kw + tq];
                a[mi][1] = Ab[(r0 + 8) * GSTW + kw + tq];
                a[mi][2] = Ab[r0 * GSTW + kw + tq + 4];
                a[mi][3] = Ab[(r0 + 8) * GSTW + kw + tq + 4];
            }
#pragma unroll
            for (int ni = 0; ni < 4; ni++) {
                int bc = wn + ni * 8 + g;
                uint32_t b0 = Bb[bc * GSTW + kw + tq];
                uint32_t b1 = Bb[bc * GSTW + kw + tq + 4];
#pragma unroll
                for (int mi = 0; mi < 2; mi++)
                    mma_bf16(acc[mi][ni][0], acc[mi][ni][1], acc[mi][ni][2], acc[mi][ni][3],
                             a[mi][0], a[mi][1], a[mi][2], a[mi][3], b0, b1);
            }
        }
        __syncthreads();
        if (i + 2 < T) issue(i + 2, i & 1);
    }

#pragma unroll
    for (int mi = 0; mi < 2; mi++) {
#pragma unroll
        for (int ni = 0; ni < 4; ni++) {
            int col = n0 + wn + ni * 8 + 2 * tq;
            int r0 = m0 + wm + mi * 16 + g;
            int r1 = r0 + 8;
            float bx = bias[col], by = bias[col + 1];
            *(uint32_t*)&C[(size_t)r0 * N + col] = pack_bf16x2(acc[mi][ni][0] + bx, acc[mi][ni][1] + by);
            *(uint32_t*)&C[(size_t)r1 * N + col] = pack_bf16x2(acc[mi][ni][2] + bx, acc[mi][ni][3] + by);
        }
    }
}

// ====== fused GEMM2 + bias + residual + LayerNorm ===========================
// out = LN(resid + A @ B^T + bias). Block tile 16x256 (full rows, grid=256),
// 8 warps each 16x32. A,B bf16; K=N=256 fixed.
#define G2BM 16
#define G2BN 256

__global__ void gemm2_ln_kernel(const __nv_bfloat16* __restrict__ A,
                                const __nv_bfloat16* __restrict__ B,
                                const float* __restrict__ bias,
                                const float* __restrict__ resid,
                                const float* __restrict__ gamma,
                                const float* __restrict__ beta,
                                float* __restrict__ out) {
    __shared__ uint32_t sm[2 * G2BM * GSTW + 2 * G2BN * GSTW];  // 10880 words
    uint32_t* As = sm;
    uint32_t* Bs = sm + 2 * G2BM * GSTW;
    float* Cs = (float*)sm;                 // epilogue alias, stride 264

    const int t = threadIdx.x;              // 256 threads
    const int wid = t >> 5;
    const int lane = t & 31;
    const int g = lane >> 2;
    const int tq = lane & 3;
    const int wn = wid * 32;
    const int m0 = blockIdx.x * G2BM;
    const int K = 256, T = 8;

    float acc[4][4];
#pragma unroll
    for (int ni = 0; ni < 4; ni++)
#pragma unroll
        for (int c = 0; c < 4; c++) acc[ni][c] = 0.f;

    auto issue = [&](int kt, int buf) {
        if (t < 64) {                       // A: 16 rows x 4 chunks
            int row = t >> 2, c16 = t & 3;
            cp_async16((uint32_t)__cvta_generic_to_shared(&As[(buf * G2BM + row) * GSTW + c16 * 4]),
                       A + (size_t)(m0 + row) * K + kt * GBK + c16 * 8);
        }
#pragma unroll
        for (int i = 0; i < 4; i++) {       // B: 256 rows x 4 chunks
            int fi = t + i * 256;
            int row = fi >> 2, c16 = fi & 3;
            cp_async16((uint32_t)__cvta_generic_to_shared(&Bs[(buf * G2BN + row) * GSTW + c16 * 4]),
                       B + (size_t)row * K + kt * GBK + c16 * 8);
        }
        cp_commit();
    };

    issue(0, 0);
    issue(1, 1);

    for (int i = 0; i < T; i++) {
        if (i + 1 < T) cp_wait<1>(); else cp_wait<0>();
        __syncthreads();

        const uint32_t* Ab = As + (i & 1) * G2BM * GSTW;
        const uint32_t* Bb = Bs + (i & 1) * G2BN * GSTW;
#pragma unroll
        for (int ks = 0; ks < 2; ks++) {
            const int kw = ks * 8;
            uint32_t a0 = Ab[g * GSTW + kw + tq];
            uint32_t a1 = Ab[(g + 8) * GSTW + kw + tq];
            uint32_t a2 = Ab[g * GSTW + kw + tq + 4];
            uint32_t a3 = Ab[(g + 8) * GSTW + kw + tq + 4];
#pragma unroll
            for (int ni = 0; ni < 4; ni++) {
                int bc = wn + ni * 8 + g;
                uint32_t b0 = Bb[bc * GSTW + kw + tq];
                uint32_t b1 = Bb[bc * GSTW + kw + tq + 4];
                mma_bf16(acc[ni][0], acc[ni][1], acc[ni][2], acc[ni][3],
                         a0, a1, a2, a3, b0, b1);
            }
        }
        __syncthreads();
        if (i + 2 < T) issue(i + 2, i & 1);
    }

    // stage acc + bias into smem (full 256-wide rows)
#pragma unroll
    for (int ni = 0; ni < 4; ni++) {
        int col = wn + ni * 8 + 2 * tq;
        float bx = bias[col], by = bias[col + 1];
        *(float2*)&Cs[g * 264 + col] = make_float2(acc[ni][0] + bx, acc[ni][1] + by);
        *(float2*)&Cs[(g + 8) * 264 + col] = make_float2(acc[ni][2] + bx, acc[ni][3] + by);
    }
    __syncthreads();

    // LayerNorm: warp w handles rows w and w+8
    for (int rr = wid; rr < G2BM; rr += 8) {
        const int grow = m0 + rr;
        float v[8], s = 0.f;
#pragma unroll
        for (int k = 0; k < 8; k++) {
            int c = lane + 32 * k;
            v[k] = Cs[rr * 264 + c] + resid[(size_t)grow * 256 + c];
            s += v[k];
        }
#pragma unroll
        for (int o = 16; o > 0; o >>= 1) s += __shfl_xor_sync(0xffffffffu, s, o);
        const float mean = s * (1.f / 256.f);
        float sq = 0.f;
#pragma unroll
        for (int k = 0; k < 8; k++) { float d = v[k] - mean; sq += d * d; }
#pragma unroll
        for (int o = 16; o > 0; o >>= 1) sq += __shfl_xor_sync(0xffffffffu, sq, o);
        const float rsig = rsqrtf(sq * (1.f / 256.f) + 1e-5f);
#pragma unroll
        for (int k = 0; k < 8; k++) {
            int c = lane + 32 * k;
            out[(size_t)grow * 256 + c] = (v[k] - mean) * rsig * gamma[c] + beta[c];
        }
    }
}

// ============== bf16 mma flash attention, block-diagonal mask ===============
// 4 warps; warp w owns query rows [16w,16w+16). m16n8k16 for S and P.V.
#define QT 64
#define KT 64
#define QSTW 20   // Qs/Ks word stride (32 bf16 = 16 words + 4 pad)
#define VTSTW 36  // Vt word stride (row=d, 64 keys = 32 words + 4 pad)
#define PSTW 36   // Ps word stride (row=query, 64 keys bf16)

__device__ __forceinline__ int lb_search(const int* __restrict__ a, int n, int v) {
    int lo = 0, hi = n;
    while (lo < hi) { int mid = (lo + hi) >> 1; if (a[mid] < v) lo = mid + 1; else hi = mid; }
    return lo;
}
__device__ __forceinline__ int ub_search(const int* __restrict__ a, int n, int v) {
    int lo = 0, hi = n;
    while (lo < hi) { int mid = (lo + hi) >> 1; if (a[mid] <= v) lo = mid + 1; else hi = mid; }
    return lo;
}

__global__ void flash_attn_kernel(const __nv_bfloat16* __restrict__ qkv,
                                  const int* __restrict__ bidx,
                                  __nv_bfloat16* __restrict__ attn_out) {
    __shared__ uint32_t Qs[QT * QSTW];
    __shared__ uint32_t Ks[KT * QSTW];
    __shared__ uint32_t Vt[HD * VTSTW];     // transposed V: [d][key]
    __shared__ uint32_t Ps[QT * PSTW];
    __shared__ int qb[QT];
    __shared__ int kb[KT];

    const int h = blockIdx.y;
    const int q0 = blockIdx.x * QT;
    const int t = threadIdx.x;            // 128 threads
    const int wid = t >> 5;
    const int lane = t & 31;
    const int g = lane >> 2;
    const int tq = lane & 3;
    const int qoff = h * HD;
    const int koff = D_MODEL + h * HD;
    const int voff = 2 * D_MODEL + h * HD;

    // load Q tile: 64 rows x 4 uint4-chunks (8 bf16 each)
#pragma unroll
    for (int i = 0; i < 2; i++) {
        int fi = t + i * 128;
        int row = fi >> 2, c = fi & 3;
        *(uint4*)&Qs[row * QSTW + c * 4] =
            *(const uint4*)&qkv[(size_t)(q0 + row) * QKV_W + qoff + c * 8];
    }
    if (t < QT) qb[t] = bidx[q0 + t];
    __syncthreads();

    // Q fragments (2 k16 steps)
    uint32_t qf[2][4];
#pragma unroll
    for (int ks = 0; ks < 2; ks++) {
        int base = (wid * 16 + g) * QSTW + ks * 8;
        int base8 = (wid * 16 + g + 8) * QSTW + ks * 8;
        qf[ks][0] = Qs[base + tq];
        qf[ks][1] = Qs[base8 + tq];
        qf[ks][2] = Qs[base + tq + 4];
        qf[ks][3] = Qs[base8 + tq + 4];
    }
    const int myb0 = qb[wid * 16 + g];
    const int myb1 = qb[wid * 16 + g + 8];
    const int seg_s = lb_search(bidx, N_TOK, qb[0]);
    const int seg_e = ub_search(bidx, N_TOK, qb[QT - 1]);

    const float scale = 0.1767766952966369f; // 1/sqrt(32)
    float m0 = 0.f, m1 = 0.f, l0 = 0.f, l1 = 0.f;  // max init 0 (valid upper bound)
    float oacc[4][4];
#pragma unroll
    for (int nt = 0; nt < 4; nt++)
#pragma unroll
        for (int c = 0; c < 4; c++) oacc[nt][c] = 0.f;

    uint16_t* VtH = (uint16_t*)Vt;

    for (int k0 = seg_s; k0 < seg_e; k0 += KT) {
        const int kt = min(KT, seg_e - k0);
        __syncthreads();
        // K tile (row-major) + V tile (transposed), zero-fill tails
#pragma unroll
        for (int i = 0; i < 2; i++) {
            int fi = t + i * 128;
            int kk = fi >> 2, c = fi & 3;
            uint4 kv = make_uint4(0, 0, 0, 0);
            uint4 vv = make_uint4(0, 0, 0, 0);
            if (kk < kt) {
                size_t base = (size_t)(k0 + kk) * QKV_W;
                kv = *(const uint4*)&qkv[base + koff + c * 8];
                vv = *(const uint4*)&qkv[base + voff + c * 8];
            }
            *(uint4*)&Ks[kk * QSTW + c * 4] = kv;
            // transpose-store V: 8 d-values of key kk
            uint32_t w[4] = {vv.x, vv.y, vv.z, vv.w};
#pragma unroll
            for (int ww = 0; ww < 4; ww++) {
                int d = c * 8 + 2 * ww;
                VtH[d * (2 * VTSTW) + kk] = (uint16_t)(w[ww] & 0xffff);
                VtH[(d + 1) * (2 * VTSTW) + kk] = (uint16_t)(w[ww] >> 16);
            }
        }
        if (t < KT) kb[t] = (t < kt) ? bidx[k0 + t] : -1;
        __syncthreads();

        // ---- S = Q K^T: 2 k16 steps x 8 n-tiles ----
        float sacc[8][4];
#pragma unroll
        for (int nt = 0; nt < 8; nt++)
#pragma unroll
            for (int c = 0; c < 4; c++) sacc[nt][c] = 0.f;
#pragma unroll
        for (int ks = 0; ks < 2; ks++) {
            const int kw = ks * 8;
#pragma unroll
            for (int nt = 0; nt < 8; nt++) {
                int kr = (nt * 8 + g) * QSTW + kw;
                mma_bf16(sacc[nt][0], sacc[nt][1], sacc[nt][2], sacc[nt][3],
                         qf[ks][0], qf[ks][1], qf[ks][2], qf[ks][3],
                         Ks[kr + tq], Ks[kr + tq + 4]);
            }
        }

        // ---- mask + row max ----
        float rmax0 = -1e30f, rmax1 = -1e30f;
#pragma unroll
        for (int nt = 0; nt < 8; nt++) {
            int c0 = nt * 8 + 2 * tq;
            int kb0 = kb[c0], kb1 = kb[c0 + 1];
            float s0 = (kb0 == myb0) ? sacc[nt][0] * scale : -1e30f;
            float s1 = (kb1 == myb0) ? sacc[nt][1] * scale : -1e30f;
            float s2 = (kb0 == myb1) ? sacc[nt][2] * scale : -1e30f;
            float s3 = (kb1 == myb1) ? sacc[nt][3] * scale : -1e30f;
            sacc[nt][0] = s0; sacc[nt][1] = s1; sacc[nt][2] = s2; sacc[nt][3] = s3;
            rmax0 = fmaxf(rmax0, fmaxf(s0, s1));
            rmax1 = fmaxf(rmax1, fmaxf(s2, s3));
        }
        rmax0 = fmaxf(rmax0, __shfl_xor_sync(0xffffffffu, rmax0, 1));
        rmax0 = fmaxf(rmax0, __shfl_xor_sync(0xffffffffu, rmax0, 2));
        rmax1 = fmaxf(rmax1, __shfl_xor_sync(0xffffffffu, rmax1, 1));
        rmax1 = fmaxf(rmax1, __shfl_xor_sync(0xffffffffu, rmax1, 2));
        const float mn0 = fmaxf(m0, rmax0);
        const float mn1 = fmaxf(m1, rmax1);
        const float al0 = __expf(m0 - mn0);
        const float al1 = __expf(m1 - mn1);
        m0 = mn0; m1 = mn1;

        // ---- exp, pack P to bf16 pairs, update l ----
        float ls0 = 0.f, ls1 = 0.f;
        const int pr0 = (wid * 16 + g) * PSTW;
        const int pr1 = (wid * 16 + g + 8) * PSTW;
#pragma unroll
        for (int nt = 0; nt < 8; nt++) {
            float p0 = __expf(sacc[nt][0] - mn0);
            float p1 = __expf(sacc[nt][1] - mn0);
            float p2 = __expf(sacc[nt][2] - mn1);
            float p3 = __expf(sacc[nt][3] - mn1);
            ls0 += p0 + p1;
            ls1 += p2 + p3;
            Ps[pr0 + nt * 4 + tq] = pack_bf16x2(p0, p1);
            Ps[pr1 + nt * 4 + tq] = pack_bf16x2(p2, p3);
        }
        ls0 += __shfl_xor_sync(0xffffffffu, ls0, 1);
        ls0 += __shfl_xor_sync(0xffffffffu, ls0, 2);
        ls1 += __shfl_xor_sync(0xffffffffu, ls1, 1);
        ls1 += __shfl_xor_sync(0xffffffffu, ls1, 2);
        l0 = l0 * al0 + ls0;
        l1 = l1 * al1 + ls1;
#pragma unroll
        for (int nt = 0; nt < 4; nt++) {
            oacc[nt][0] *= al0; oacc[nt][1] *= al0;
            oacc[nt][2] *= al1; oacc[nt][3] *= al1;
        }
        __syncwarp();  // warp-local P rows visible

        // ---- O += P V: 4 k16 steps x 4 n-tiles ----
#pragma unroll
        for (int ks = 0; ks < 4; ks++) {
            const int kw = ks * 8;
            uint32_t a0 = Ps[pr0 + kw + tq];
            uint32_t a1 = Ps[pr1 + kw + tq];
            uint32_t a2 = Ps[pr0 + kw + tq + 4];
            uint32_t a3 = Ps[pr1 + kw + tq + 4];
#pragma unroll
            for (int nt = 0; nt < 4; nt++) {
                int vr = (nt * 8 + g) * VTSTW + kw;
                mma_bf16(oacc[nt][0], oacc[nt][1], oacc[nt][2], oacc[nt][3],
                         a0, a1, a2, a3, Vt[vr + tq], Vt[vr + tq + 4]);
            }
        }
    }

    const float i0 = 1.f / l0;
    const float i1 = 1.f / l1;
    const int r0 = q0 + wid * 16 + g;
    const int r1 = r0 + 8;
#pragma unroll
    for (int nt = 0; nt < 4; nt++) {
        int col = h * HD + nt * 8 + 2 * tq;
        *(uint32_t*)&attn_out[(size_t)r0 * D_MODEL + col] = pack_bf16x2(oacc[nt][0] * i0, oacc[nt][1] * i0);
        *(uint32_t*)&attn_out[(size_t)r1 * D_MODEL + col] = pack_bf16x2(oacc[nt][2] * i1, oacc[nt][3] * i1);
    }
}

// ---------------- launch ----------------------------------------------------
extern "C" void kernel_launch(void* const* d_in, const int* in_sizes, int n_in,
                              void* d_out, int out_size) {
    const float* slots    = (const float*)d_in[0];
    const int*   batch_ix = (const int*)d_in[1];
    const float* w_in     = (const float*)d_in[2];
    const float* b_in     = (const float*)d_in[3];
    const float* w_out    = (const float*)d_in[4];
    const float* b_out    = (const float*)d_in[5];
    const float* ln_gamma = (const float*)d_in[6];
    const float* ln_beta  = (const float*)d_in[7];
    float* out = (float*)d_out;

    __nv_bfloat16* qkv_bf;   cudaGetSymbolAddress((void**)&qkv_bf,   g_qkv_bf);
    __nv_bfloat16* attn_bf;  cudaGetSymbolAddress((void**)&attn_bf,  g_attn_bf);
    __nv_bfloat16* slots_bf; cudaGetSymbolAddress((void**)&slots_bf, g_slots_bf);
    __nv_bfloat16* win_bf;   cudaGetSymbolAddress((void**)&win_bf,   g_win_bf);
    __nv_bfloat16* wout_bf;  cudaGetSymbolAddress((void**)&wout_bf,  g_wout_bf);

    // 0) convert inputs to bf16 (slots, w_in, w_out)
    {
        const int n0 = N_TOK * D_MODEL, n1 = QKV_W * D_MODEL, n2 = D_MODEL * D_MODEL;
        const int total4 = (n0 + n1 + n2) / 4;
        cvt_bf16_kernel<<<(total4 + 255) / 256, 256>>>(slots, slots_bf, n0,
                                                       w_in, win_bf, n1,
                                                       w_out, wout_bf, n2);
    }
    // 1) QKV projection (bf16 in/out): qkv = slots @ w_in^T + b_in
    {
        dim3 grid(QKV_W / GBN, N_TOK / GBM);
        gemm_bf16_kernel<<<grid, 256>>>(slots_bf, win_bf, b_in, qkv_bf,
                                        N_TOK, QKV_W, D_MODEL);
    }
    // 2) block-diagonal flash attention (bf16 mma)
    {
        dim3 grid(N_TOK / QT, H_HEADS);
        flash_attn_kernel<<<grid, 128>>>(qkv_bf, batch_ix, attn_bf);
    }
    // 3) fused out-projection + bias + residual + LayerNorm
    gemm2_ln_kernel<<<N_TOK / G2BM, 256>>>(attn_bf, wout_bf, b_out, slots,
                                           ln_gamma, ln_beta, out);
}

// round 7
// speedup vs baseline: 5.1224x; 1.0773x over previous
#include <cuda_runtime.h>
#include <cuda_bf16.h>
#include <math.h>
#include <stdint.h>

#define N_TOK 4096
#define D_MODEL 256
#define H_HEADS 8
#define HD 32
#define QKV_W 768

// ---------------- scratch (device globals; no allocation allowed) ----------
__device__ __nv_bfloat16 g_qkv_bf[N_TOK * QKV_W];      // bf16 q|k|v
__device__ __nv_bfloat16 g_attn_bf[N_TOK * D_MODEL];   // attention out (bf16)
__device__ __nv_bfloat16 g_slots_bf[N_TOK * D_MODEL];
__device__ __nv_bfloat16 g_win_bf[QKV_W * D_MODEL];
__device__ __nv_bfloat16 g_wout_bf[D_MODEL * D_MODEL];

// =================== mma / cp.async helpers ================================
__device__ __forceinline__ void mma_bf16(float& d0, float& d1, float& d2, float& d3,
                                         uint32_t a0, uint32_t a1, uint32_t a2, uint32_t a3,
                                         uint32_t b0, uint32_t b1) {
    asm volatile("mma.sync.aligned.m16n8k16.row.col.f32.bf16.bf16.f32 "
                 "{%0,%1,%2,%3}, {%4,%5,%6,%7}, {%8,%9}, {%0,%1,%2,%3};"
                 : "+f"(d0), "+f"(d1), "+f"(d2), "+f"(d3)
                 : "r"(a0), "r"(a1), "r"(a2), "r"(a3), "r"(b0), "r"(b1));
}

__device__ __forceinline__ void cp_async16(uint32_t dst, const void* src) {
    asm volatile("cp.async.cg.shared.global [%0], [%1], 16;" :: "r"(dst), "l"(src));
}
__device__ __forceinline__ void cp_commit() {
    asm volatile("cp.async.commit_group;");
}
template <int Nwait>
__device__ __forceinline__ void cp_wait() {
    asm volatile("cp.async.wait_group %0;" :: "n"(Nwait));
}

// pack two fp32 into one bf16x2 register (lo -> low half, hi -> high half)
__device__ __forceinline__ uint32_t pack_bf16x2(float lo, float hi) {
    uint32_t r;
    asm("cvt.rn.bf16x2.f32 %0, %1, %2;" : "=r"(r) : "f"(hi), "f"(lo));
    return r;
}

// =================== fp32 -> bf16 conversion (3 arrays, one launch) ========
__global__ void cvt_bf16_kernel(const float* __restrict__ s0, __nv_bfloat16* __restrict__ d0, int n0,
                                const float* __restrict__ s1, __nv_bfloat16* __restrict__ d1, int n1,
                                const float* __restrict__ s2, __nv_bfloat16* __restrict__ d2, int n2) {
    int i = blockIdx.x * blockDim.x + threadIdx.x;  // one float4 per thread
    const float* s;
    __nv_bfloat16* d;
    int off;
    int q0 = n0 >> 2, q1 = q0 + (n1 >> 2), q2 = q1 + (n2 >> 2);
    if (i >= q2) return;
    if (i < q0) { s = s0; d = d0; off = i * 4; }
    else if (i < q1) { s = s1; d = d1; off = (i - q0) * 4; }
    else { s = s2; d = d2; off = (i - q1) * 4; }
    float4 v = *(const float4*)&s[off];
    *(uint32_t*)&d[off] = pack_bf16x2(v.x, v.y);
    *(uint32_t*)&d[off + 2] = pack_bf16x2(v.z, v.w);
}

// ===== bf16 GEMM1: C[M,N] = A[M,K] @ B[N,K]^T + bias, bf16 output ==========
// Block tile 128x64, 8 warps (4x2), warp tile 32x32, BK=32, m16n8k16,
// cp.async TRIPLE-buffered. Smem row stride 20 words: conflict-free frags.
#define GBM 128
#define GBN 64
#define GBK 32
#define GSTW 20

__global__ void gemm_bf16_kernel(const __nv_bfloat16* __restrict__ A,
                                 const __nv_bfloat16* __restrict__ B,
                                 const float* __restrict__ bias,
                                 __nv_bfloat16* __restrict__ C,
                                 int M, int N, int K) {
    __shared__ uint32_t As[3 * GBM * GSTW];
    __shared__ uint32_t Bs[3 * GBN * GSTW];

    const int t = threadIdx.x;            // 256 threads
    const int wid = t >> 5;
    const int lane = t & 31;
    const int g = lane >> 2;
    const int tq = lane & 3;
    const int wm = (wid & 3) * 32;
    const int wn = (wid >> 2) * 32;
    const int m0 = blockIdx.y * GBM;
    const int n0 = blockIdx.x * GBN;

    float acc[2][4][4];
#pragma unroll
    for (int mi = 0; mi < 2; mi++)
#pragma unroll
        for (int ni = 0; ni < 4; ni++)
#pragma unroll
            for (int c = 0; c < 4; c++) acc[mi][ni][c] = 0.f;

    const int T = K / GBK;

    auto issue = [&](int kt, int buf) {
        const __nv_bfloat16* Ab = A + (size_t)m0 * K + kt * GBK;
#pragma unroll
        for (int i = 0; i < 2; i++) {
            int fi = t + i * 256;
            int row = fi >> 2, c16 = fi & 3;
            cp_async16((uint32_t)__cvta_generic_to_shared(&As[(buf * GBM + row) * GSTW + c16 * 4]),
                       Ab + (size_t)row * K + c16 * 8);
        }
        const __nv_bfloat16* Bb = B + (size_t)n0 * K + kt * GBK;
        {
            int row = t >> 2, c16 = t & 3;
            cp_async16((uint32_t)__cvta_generic_to_shared(&Bs[(buf * GBN + row) * GSTW + c16 * 4]),
                       Bb + (size_t)row * K + c16 * 8);
        }
        cp_commit();
    };

    issue(0, 0);
    if (T > 1) issue(1, 1);
    if (T > 2) issue(2, 2);

    for (int i = 0; i < T; i++) {
        if (i + 2 < T) cp_wait<2>();
        else if (i + 1 < T) cp_wait<1>();
        else cp_wait<0>();
        __syncthreads();

        const uint32_t* Ab = As + (i % 3) * GBM * GSTW;
        const uint32_t* Bb = Bs + (i % 3) * GBN * GSTW;
#pragma unroll
        for (int ks = 0; ks < 2; ks++) {
            const int kw = ks * 8;
            uint32_t a[2][4];
#pragma unroll
            for (int mi = 0; mi < 2; mi++) {
                int r0 = wm + mi * 16 + g;
                a[mi][0] = Ab[r0 * GSTW + kw + tq];
                a[mi][1] = Ab[(r0 + 8) * GSTW + kw + tq];
                a[mi][2] = Ab[r0 * GSTW + kw + tq + 4];
                a[mi][3] = Ab[(r0 + 8) * GSTW + kw + tq + 4];
            }
#pragma unroll
            for (int ni = 0; ni < 4; ni++) {
                int bc = wn + ni * 8 + g;
                uint32_t b0 = Bb[bc * GSTW + kw + tq];
                uint32_t b1 = Bb[bc * GSTW + kw + tq + 4];
#pragma unroll
                for (int mi = 0; mi < 2; mi++)
                    mma_bf16(acc[mi][ni][0], acc[mi][ni][1], acc[mi][ni][2], acc[mi][ni][3],
                             a[mi][0], a[mi][1], a[mi][2], a[mi][3], b0, b1);
            }
        }
        __syncthreads();
        if (i + 3 < T) issue(i + 3, (i + 3) % 3);
    }

#pragma unroll
    for (int mi = 0; mi < 2; mi++) {
#pragma unroll
        for (int ni = 0; ni < 4; ni++) {
            int col = n0 + wn + ni * 8 + 2 * tq;
            int r0 = m0 + wm + mi * 16 + g;
            int r1 = r0 + 8;
            float bx = bias[col], by = bias[col + 1];
            *(uint32_t*)&C[(size_t)r0 * N + col] = pack_bf16x2(acc[mi][ni][0] + bx, acc[mi][ni][1] + by);
            *(uint32_t*)&C[(size_t)r1 * N + col] = pack_bf16x2(acc[mi][ni][2] + bx, acc[mi][ni][3] + by);
        }
    }
}

// ====== fused GEMM2 + bias + residual + LayerNorm ===========================
// out = LN(resid + A @ B^T + bias). Block tile 32x256 (full rows, grid=128),
// 8 warps (2m x 4n), warp tile 16x64. Depth-3 cp.async pipeline; resid and
// bias/gamma/beta are prefetched into smem alongside the stage loads so the
// epilogue has no global-load latency chain.
#define G2BM 32
#define G2BN 256
#define G2AB (3 * G2BM * GSTW + 3 * G2BN * GSTW)      // 17280 words
#define G2RES G2AB                                     // resid: 8192 words
#define G2PAR (G2AB + 32 * 256)                        // bias|gamma|beta: 768
#define G2WORDS (G2PAR + 768)                          // total 26240 words

__global__ void gemm2_ln_kernel(const __nv_bfloat16* __restrict__ A,
                                const __nv_bfloat16* __restrict__ B,
                                const float* __restrict__ bias,
                                const float* __restrict__ resid,
                                const float* __restrict__ gamma,
                                const float* __restrict__ beta,
                                float* __restrict__ out) {
    extern __shared__ uint32_t sm[];
    uint32_t* As = sm;                      // [3][G2BM][GSTW]
    uint32_t* Bs = sm + 3 * G2BM * GSTW;    // [3][G2BN][GSTW]
    float* Rs = (float*)(sm + G2RES);       // [32][256] residual
    float* Ps = (float*)(sm + G2PAR);       // bias[256] gamma[256] beta[256]
    float* Cs = (float*)sm;                 // epilogue alias, stride 264

    const int t = threadIdx.x;              // 256 threads
    const int wid = t >> 5;
    const int lane = t & 31;
    const int g = lane >> 2;
    const int tq = lane & 3;
    const int wm = (wid & 1) * 16;
    const int wn = (wid >> 1) * 64;
    const int m0 = blockIdx.x * G2BM;
    const int K = 256, T = 8;

    float acc[8][4];
#pragma unroll
    for (int ni = 0; ni < 8; ni++)
#pragma unroll
        for (int c = 0; c < 4; c++) acc[ni][c] = 0.f;

    auto issue = [&](int kt, int buf) {
        if (t < 128) {                      // A: 32 rows x 4 chunks
            int row = t >> 2, c16 = t & 3;
            cp_async16((uint32_t)__cvta_generic_to_shared(&As[(buf * G2BM + row) * GSTW + c16 * 4]),
                       A + (size_t)(m0 + row) * K + kt * GBK + c16 * 8);
        }
#pragma unroll
        for (int i = 0; i < 4; i++) {       // B: 256 rows x 4 chunks
            int fi = t + i * 256;
            int row = fi >> 2, c16 = fi & 3;
            cp_async16((uint32_t)__cvta_generic_to_shared(&Bs[(buf * G2BN + row) * GSTW + c16 * 4]),
                       B + (size_t)row * K + kt * GBK + c16 * 8);
        }
        // resid rows [kt*4, kt*4+4): 4 rows x 64 chunks, 1 per thread
        {
            int rr = kt * 4 + (t >> 6);
            int c4 = t & 63;
            cp_async16((uint32_t)__cvta_generic_to_shared(&Rs[rr * 256 + c4 * 4]),
                       resid + (size_t)(m0 + rr) * 256 + c4 * 4);
        }
        if (kt == 0) {                      // params: 192 chunks
            if (t < 64)
                cp_async16((uint32_t)__cvta_generic_to_shared(&Ps[t * 4]), bias + t * 4);
            else if (t < 128)
                cp_async16((uint32_t)__cvta_generic_to_shared(&Ps[256 + (t - 64) * 4]), gamma + (t - 64) * 4);
            else if (t < 192)
                cp_async16((uint32_t)__cvta_generic_to_shared(&Ps[512 + (t - 128) * 4]), beta + (t - 128) * 4);
        }
        cp_commit();
    };

    issue(0, 0);
    issue(1, 1);
    issue(2, 2);

    for (int i = 0; i < T; i++) {
        if (i + 2 < T) cp_wait<2>();
        else if (i + 1 < T) cp_wait<1>();
        else cp_wait<0>();
        __syncthreads();

        const uint32_t* Ab = As + (i % 3) * G2BM * GSTW;
        const uint32_t* Bb = Bs + (i % 3) * G2BN * GSTW;
#pragma unroll
        for (int ks = 0; ks < 2; ks++) {
            const int kw = ks * 8;
            uint32_t a0 = Ab[(wm + g) * GSTW + kw + tq];
            uint32_t a1 = Ab[(wm + g + 8) * GSTW + kw + tq];
            uint32_t a2 = Ab[(wm + g) * GSTW + kw + tq + 4];
            uint32_t a3 = Ab[(wm + g + 8) * GSTW + kw + tq + 4];
#pragma unroll
            for (int ni = 0; ni < 8; ni++) {
                int bc = wn + ni * 8 + g;
                uint32_t b0 = Bb[bc * GSTW + kw + tq];
                uint32_t b1 = Bb[bc * GSTW + kw + tq + 4];
                mma_bf16(acc[ni][0], acc[ni][1], acc[ni][2], acc[ni][3],
                         a0, a1, a2, a3, b0, b1);
            }
        }
        __syncthreads();
        if (i + 3 < T) issue(i + 3, (i + 3) % 3);
    }

    // stage acc + bias into smem (full 256-wide rows; aliases AB buffers)
#pragma unroll
    for (int ni = 0; ni < 8; ni++) {
        int col = wn + ni * 8 + 2 * tq;
        float bx = Ps[col], by = Ps[col + 1];
        *(float2*)&Cs[(wm + g) * 264 + col] = make_float2(acc[ni][0] + bx, acc[ni][1] + by);
        *(float2*)&Cs[(wm + g + 8) * 264 + col] = make_float2(acc[ni][2] + bx, acc[ni][3] + by);
    }
    __syncthreads();

    // LayerNorm: warp w handles rows [4w, 4w+4); all operands in smem
#pragma unroll
    for (int rr = wid * 4; rr < wid * 4 + 4; rr++) {
        float v[8], s = 0.f;
#pragma unroll
        for (int k = 0; k < 8; k++) {
            int c = lane + 32 * k;
            v[k] = Cs[rr * 264 + c] + Rs[rr * 256 + c];
            s += v[k];
        }
#pragma unroll
        for (int o = 16; o > 0; o >>= 1) s += __shfl_xor_sync(0xffffffffu, s, o);
        const float mean = s * (1.f / 256.f);
        float sq = 0.f;
#pragma unroll
        for (int k = 0; k < 8; k++) { float d = v[k] - mean; sq += d * d; }
#pragma unroll
        for (int o = 16; o > 0; o >>= 1) sq += __shfl_xor_sync(0xffffffffu, sq, o);
        const float rsig = rsqrtf(sq * (1.f / 256.f) + 1e-5f);
#pragma unroll
        for (int k = 0; k < 8; k++) {
            int c = lane + 32 * k;
            out[(size_t)(m0 + rr) * 256 + c] = (v[k] - mean) * rsig * Ps[256 + c] + Ps[512 + c];
        }
    }
}

// ============== bf16 mma flash attention, block-diagonal mask ===============
// 4 warps; warp w owns query rows [16w,16w+16). m16n8k16 for S and P.V.
#define QT 64
#define KT 64
#define QSTW 20   // Qs/Ks word stride (32 bf16 = 16 words + 4 pad)
#define VTSTW 36  // Vt word stride (row=d, 64 keys = 32 words + 4 pad)
#define PSTW 36   // Ps word stride (row=query, 64 keys bf16)

__device__ __forceinline__ int lb_search(const int* __restrict__ a, int n, int v) {
    int lo = 0, hi = n;
    while (lo < hi) { int mid = (lo + hi) >> 1; if (a[mid] < v) lo = mid + 1; else hi = mid; }
    return lo;
}
__device__ __forceinline__ int ub_search(const int* __restrict__ a, int n, int v) {
    int lo = 0, hi = n;
    while (lo < hi) { int mid = (lo + hi) >> 1; if (a[mid] <= v) lo = mid + 1; else hi = mid; }
    return lo;
}

__global__ void flash_attn_kernel(const __nv_bfloat16* __restrict__ qkv,
                                  const int* __restrict__ bidx,
                                  __nv_bfloat16* __restrict__ attn_out) {
    __shared__ uint32_t Qs[QT * QSTW];
    __shared__ uint32_t Ks[KT * QSTW];
    __shared__ uint32_t Vt[HD * VTSTW];     // transposed V: [d][key]
    __shared__ uint32_t Pp[QT * PSTW];
    __shared__ int qb[QT];
    __shared__ int kb[KT];

    const int h = blockIdx.y;
    const int q0 = blockIdx.x * QT;
    const int t = threadIdx.x;            // 128 threads
    const int wid = t >> 5;
    const int lane = t & 31;
    const int g = lane >> 2;
    const int tq = lane & 3;
    const int qoff = h * HD;
    const int koff = D_MODEL + h * HD;
    const int voff = 2 * D_MODEL + h * HD;

    // load Q tile: 64 rows x 4 uint4-chunks (8 bf16 each)
#pragma unroll
    for (int i = 0; i < 2; i++) {
        int fi = t + i * 128;
        int row = fi >> 2, c = fi & 3;
        *(uint4*)&Qs[row * QSTW + c * 4] =
            *(const uint4*)&qkv[(size_t)(q0 + row) * QKV_W + qoff + c * 8];
    }
    if (t < QT) qb[t] = bidx[q0 + t];
    __syncthreads();

    // Q fragments (2 k16 steps)
    uint32_t qf[2][4];
#pragma unroll
    for (int ks = 0; ks < 2; ks++) {
        int base = (wid * 16 + g) * QSTW + ks * 8;
        int base8 = (wid * 16 + g + 8) * QSTW + ks * 8;
        qf[ks][0] = Qs[base + tq];
        qf[ks][1] = Qs[base8 + tq];
        qf[ks][2] = Qs[base + tq + 4];
        qf[ks][3] = Qs[base8 + tq + 4];
    }
    const int myb0 = qb[wid * 16 + g];
    const int myb1 = qb[wid * 16 + g + 8];
    const int seg_s = lb_search(bidx, N_TOK, qb[0]);
    const int seg_e = ub_search(bidx, N_TOK, qb[QT - 1]);

    const float scale = 0.1767766952966369f; // 1/sqrt(32)
    float m0 = 0.f, m1 = 0.f, l0 = 0.f, l1 = 0.f;  // max init 0 (valid upper bound)
    float oacc[4][4];
#pragma unroll
    for (int nt = 0; nt < 4; nt++)
#pragma unroll
        for (int c = 0; c < 4; c++) oacc[nt][c] = 0.f;

    uint16_t* VtH = (uint16_t*)Vt;

    for (int k0 = seg_s; k0 < seg_e; k0 += KT) {
        const int kt = min(KT, seg_e - k0);
        __syncthreads();
        // K tile (row-major) + V tile (transposed), zero-fill tails
#pragma unroll
        for (int i = 0; i < 2; i++) {
            int fi = t + i * 128;
            int kk = fi >> 2, c = fi & 3;
            uint4 kv = make_uint4(0, 0, 0, 0);
            uint4 vv = make_uint4(0, 0, 0, 0);
            if (kk < kt) {
                size_t base = (size_t)(k0 + kk) * QKV_W;
                kv = *(const uint4*)&qkv[base + koff + c * 8];
                vv = *(const uint4*)&qkv[base + voff + c * 8];
            }
            *(uint4*)&Ks[kk * QSTW + c * 4] = kv;
            // transpose-store V: 8 d-values of key kk
            uint32_t w[4] = {vv.x, vv.y, vv.z, vv.w};
#pragma unroll
            for (int ww = 0; ww < 4; ww++) {
                int d = c * 8 + 2 * ww;
                VtH[d * (2 * VTSTW) + kk] = (uint16_t)(w[ww] & 0xffff);
                VtH[(d + 1) * (2 * VTSTW) + kk] = (uint16_t)(w[ww] >> 16);
            }
        }
        if (t < KT) kb[t] = (t < kt) ? bidx[k0 + t] : -1;
        __syncthreads();

        // ---- S = Q K^T: 2 k16 steps x 8 n-tiles ----
        float sacc[8][4];
#pragma unroll
        for (int nt = 0; nt < 8; nt++)
#pragma unroll
            for (int c = 0; c < 4; c++) sacc[nt][c] = 0.f;
#pragma unroll
        for (int ks = 0; ks < 2; ks++) {
            const int kw = ks * 8;
#pragma unroll
            for (int nt = 0; nt < 8; nt++) {
                int kr = (nt * 8 + g) * QSTW + kw;
                mma_bf16(sacc[nt][0], sacc[nt][1], sacc[nt][2], sacc[nt][3],
                         qf[ks][0], qf[ks][1], qf[ks][2], qf[ks][3],
                         Ks[kr + tq], Ks[kr + tq + 4]);
            }
        }

        // ---- mask + row max ----
        float rmax0 = -1e30f, rmax1 = -1e30f;
#pragma unroll
        for (int nt = 0; nt < 8; nt++) {
            int c0 = nt * 8 + 2 * tq;
            int kb0 = kb[c0], kb1 = kb[c0 + 1];
            float s0 = (kb0 == myb0) ? sacc[nt][0] * scale : -1e30f;
            float s1 = (kb1 == myb0) ? sacc[nt][1] * scale : -1e30f;
            float s2 = (kb0 == myb1) ? sacc[nt][2] * scale : -1e30f;
            float s3 = (kb1 == myb1) ? sacc[nt][3] * scale : -1e30f;
            sacc[nt][0] = s0; sacc[nt][1] = s1; sacc[nt][2] = s2; sacc[nt][3] = s3;
            rmax0 = fmaxf(rmax0, fmaxf(s0, s1));
            rmax1 = fmaxf(rmax1, fmaxf(s2, s3));
        }
        rmax0 = fmaxf(rmax0, __shfl_xor_sync(0xffffffffu, rmax0, 1));
        rmax0 = fmaxf(rmax0, __shfl_xor_sync(0xffffffffu, rmax0, 2));
        rmax1 = fmaxf(rmax1, __shfl_xor_sync(0xffffffffu, rmax1, 1));
        rmax1 = fmaxf(rmax1, __shfl_xor_sync(0xffffffffu, rmax1, 2));
        const float mn0 = fmaxf(m0, rmax0);
        const float mn1 = fmaxf(m1, rmax1);
        const float al0 = __expf(m0 - mn0);
        const float al1 = __expf(m1 - mn1);
        m0 = mn0; m1 = mn1;

        // ---- exp, pack P to bf16 pairs, update l ----
        float ls0 = 0.f, ls1 = 0.f;
        const int pr0 = (wid * 16 + g) * PSTW;
        const int pr1 = (wid * 16 + g + 8) * PSTW;
#pragma unroll
        for (int nt = 0; nt < 8; nt++) {
            float p0 = __expf(sacc[nt][0] - mn0);
            float p1 = __expf(sacc[nt][1] - mn0);
            float p2 = __expf(sacc[nt][2] - mn1);
            float p3 = __expf(sacc[nt][3] - mn1);
            ls0 += p0 + p1;
            ls1 += p2 + p3;
            Pp[pr0 + nt * 4 + tq] = pack_bf16x2(p0, p1);
            Pp[pr1 + nt * 4 + tq] = pack_bf16x2(p2, p3);
        }
        ls0 += __shfl_xor_sync(0xffffffffu, ls0, 1);
        ls0 += __shfl_xor_sync(0xffffffffu, ls0, 2);
        ls1 += __shfl_xor_sync(0xffffffffu, ls1, 1);
        ls1 += __shfl_xor_sync(0xffffffffu, ls1, 2);
        l0 = l0 * al0 + ls0;
        l1 = l1 * al1 + ls1;
#pragma unroll
        for (int nt = 0; nt < 4; nt++) {
            oacc[nt][0] *= al0; oacc[nt][1] *= al0;
            oacc[nt][2] *= al1; oacc[nt][3] *= al1;
        }
        __syncwarp();  // warp-local P rows visible

        // ---- O += P V: 4 k16 steps x 4 n-tiles ----
#pragma unroll
        for (int ks = 0; ks < 4; ks++) {
            const int kw = ks * 8;
            uint32_t a0 = Pp[pr0 + kw + tq];
            uint32_t a1 = Pp[pr1 + kw + tq];
            uint32_t a2 = Pp[pr0 + kw + tq + 4];
            uint32_t a3 = Pp[pr1 + kw + tq + 4];
#pragma unroll
            for (int nt = 0; nt < 4; nt++) {
                int vr = (nt * 8 + g) * VTSTW + kw;
                mma_bf16(oacc[nt][0], oacc[nt][1], oacc[nt][2], oacc[nt][3],
                         a0, a1, a2, a3, Vt[vr + tq], Vt[vr + tq + 4]);
            }
        }
    }

    const float i0 = 1.f / l0;
    const float i1 = 1.f / l1;
    const int r0 = q0 + wid * 16 + g;
    const int r1 = r0 + 8;
#pragma unroll
    for (int nt = 0; nt < 4; nt++) {
        int col = h * HD + nt * 8 + 2 * tq;
        *(uint32_t*)&attn_out[(size_t)r0 * D_MODEL + col] = pack_bf16x2(oacc[nt][0] * i0, oacc[nt][1] * i0);
        *(uint32_t*)&attn_out[(size_t)r1 * D_MODEL + col] = pack_bf16x2(oacc[nt][2] * i1, oacc[nt][3] * i1);
    }
}

// ---------------- launch ----------------------------------------------------
extern "C" void kernel_launch(void* const* d_in, const int* in_sizes, int n_in,
                              void* d_out, int out_size) {
    const float* slots    = (const float*)d_in[0];
    const int*   batch_ix = (const int*)d_in[1];
    const float* w_in     = (const float*)d_in[2];
    const float* b_in     = (const float*)d_in[3];
    const float* w_out    = (const float*)d_in[4];
    const float* b_out    = (const float*)d_in[5];
    const float* ln_gamma = (const float*)d_in[6];
    const float* ln_beta  = (const float*)d_in[7];
    float* out = (float*)d_out;

    __nv_bfloat16* qkv_bf;   cudaGetSymbolAddress((void**)&qkv_bf,   g_qkv_bf);
    __nv_bfloat16* attn_bf;  cudaGetSymbolAddress((void**)&attn_bf,  g_attn_bf);
    __nv_bfloat16* slots_bf; cudaGetSymbolAddress((void**)&slots_bf, g_slots_bf);
    __nv_bfloat16* win_bf;   cudaGetSymbolAddress((void**)&win_bf,   g_win_bf);
    __nv_bfloat16* wout_bf;  cudaGetSymbolAddress((void**)&wout_bf,  g_wout_bf);

    // 0) convert inputs to bf16 (slots, w_in, w_out)
    {
        const int n0 = N_TOK * D_MODEL, n1 = QKV_W * D_MODEL, n2 = D_MODEL * D_MODEL;
        const int total4 = (n0 + n1 + n2) / 4;
        cvt_bf16_kernel<<<(total4 + 255) / 256, 256>>>(slots, slots_bf, n0,
                                                       w_in, win_bf, n1,
                                                       w_out, wout_bf, n2);
    }
    // 1) QKV projection (bf16 in/out): qkv = slots @ w_in^T + b_in
    {
        dim3 grid(QKV_W / GBN, N_TOK / GBM);
        gemm_bf16_kernel<<<grid, 256>>>(slots_bf, win_bf, b_in, qkv_bf,
                                        N_TOK, QKV_W, D_MODEL);
    }
    // 2) block-diagonal flash attention (bf16 mma)
    {
        dim3 grid(N_TOK / QT, H_HEADS);
        flash_attn_kernel<<<grid, 128>>>(qkv_bf, batch_ix, attn_bf);
    }
    // 3) fused out-projection + bias + residual + LayerNorm (dynamic smem)
    {
        const int smem_bytes = G2WORDS * (int)sizeof(uint32_t);  // ~105 KB
        cudaFuncSetAttribute(gemm2_ln_kernel,
                             cudaFuncAttributeMaxDynamicSharedMemorySize, smem_bytes);
        gemm2_ln_kernel<<<N_TOK / G2BM, 256, smem_bytes>>>(attn_bf, wout_bf, b_out, slots,
                                                           ln_gamma, ln_beta, out);
    }
}

// round 11
// speedup vs baseline: 5.2789x; 1.0305x over previous
#include <cuda_runtime.h>
#include <cuda_bf16.h>
#include <math.h>
#include <stdint.h>

#define N_TOK 4096
#define D_MODEL 256
#define H_HEADS 8
#define HD 32
#define QKV_W 768

// ---------------- scratch (device globals; no allocation allowed) ----------
__device__ __nv_bfloat16 g_qkv_bf[N_TOK * QKV_W];      // bf16 q|k|v
__device__ __nv_bfloat16 g_attn_bf[N_TOK * D_MODEL];   // attention out (bf16)
__device__ __nv_bfloat16 g_slots_bf[N_TOK * D_MODEL];
__device__ __nv_bfloat16 g_win_bf[QKV_W * D_MODEL];
__device__ __nv_bfloat16 g_wout_bf[D_MODEL * D_MODEL];

// =================== mma / cp.async / ldmatrix helpers =====================
__device__ __forceinline__ void mma_bf16(float& d0, float& d1, float& d2, float& d3,
                                         uint32_t a0, uint32_t a1, uint32_t a2, uint32_t a3,
                                         uint32_t b0, uint32_t b1) {
    asm volatile("mma.sync.aligned.m16n8k16.row.col.f32.bf16.bf16.f32 "
                 "{%0,%1,%2,%3}, {%4,%5,%6,%7}, {%8,%9}, {%0,%1,%2,%3};"
                 : "+f"(d0), "+f"(d1), "+f"(d2), "+f"(d3)
                 : "r"(a0), "r"(a1), "r"(a2), "r"(a3), "r"(b0), "r"(b1));
}

__device__ __forceinline__ void cp_async16(uint32_t dst, const void* src) {
    asm volatile("cp.async.cg.shared.global [%0], [%1], 16;" :: "r"(dst), "l"(src));
}
__device__ __forceinline__ void cp_commit() {
    asm volatile("cp.async.commit_group;");
}
template <int Nwait>
__device__ __forceinline__ void cp_wait() {
    asm volatile("cp.async.wait_group %0;" :: "n"(Nwait));
}

// transposed 8x8 b16 x4 loads (for V^T fragments)
__device__ __forceinline__ void ldsm_x4_trans(uint32_t& r0, uint32_t& r1,
                                              uint32_t& r2, uint32_t& r3, uint32_t addr) {
    asm volatile("ldmatrix.sync.aligned.m8n8.x4.trans.shared.b16 {%0,%1,%2,%3}, [%4];"
                 : "=r"(r0), "=r"(r1), "=r"(r2), "=r"(r3) : "r"(addr));
}

// pack two fp32 into one bf16x2 register (lo -> low half, hi -> high half)
__device__ __forceinline__ uint32_t pack_bf16x2(float lo, float hi) {
    uint32_t r;
    asm("cvt.rn.bf16x2.f32 %0, %1, %2;" : "=r"(r) : "f"(hi), "f"(lo));
    return r;
}

// =================== fp32 -> bf16 conversion (3 arrays, one launch) ========
__global__ void cvt_bf16_kernel(const float* __restrict__ s0, __nv_bfloat16* __restrict__ d0, int n0,
                                const float* __restrict__ s1, __nv_bfloat16* __restrict__ d1, int n1,
                                const float* __restrict__ s2, __nv_bfloat16* __restrict__ d2, int n2) {
    int i = blockIdx.x * blockDim.x + threadIdx.x;  // one float4 per thread
    const float* s;
    __nv_bfloat16* d;
    int off;
    int q0 = n0 >> 2, q1 = q0 + (n1 >> 2), q2 = q1 + (n2 >> 2);
    if (i >= q2) return;
    if (i < q0) { s = s0; d = d0; off = i * 4; }
    else if (i < q1) { s = s1; d = d1; off = (i - q0) * 4; }
    else { s = s2; d = d2; off = (i - q1) * 4; }
    float4 v = *(const float4*)&s[off];
    *(uint32_t*)&d[off] = pack_bf16x2(v.x, v.y);
    *(uint32_t*)&d[off + 2] = pack_bf16x2(v.z, v.w);
}

// ===== bf16 GEMM1: C[M,N] = A[M,K] @ B[N,K]^T + bias, bf16 output ==========
#define GBM 128
#define GBN 64
#define GBK 32
#define GSTW 20

__global__ void gemm_bf16_kernel(const __nv_bfloat16* __restrict__ A,
                                 const __nv_bfloat16* __restrict__ B,
                                 const float* __restrict__ bias,
                                 __nv_bfloat16* __restrict__ C,
                                 int M, int N, int K) {
    __shared__ uint32_t As[3 * GBM * GSTW];
    __shared__ uint32_t Bs[3 * GBN * GSTW];

    const int t = threadIdx.x;            // 256 threads
    const int wid = t >> 5;
    const int lane = t & 31;
    const int g = lane >> 2;
    const int tq = lane & 3;
    const int wm = (wid & 3) * 32;
    const int wn = (wid >> 2) * 32;
    const int m0 = blockIdx.y * GBM;
    const int n0 = blockIdx.x * GBN;

    float acc[2][4][4];
#pragma unroll
    for (int mi = 0; mi < 2; mi++)
#pragma unroll
        for (int ni = 0; ni < 4; ni++)
#pragma unroll
            for (int c = 0; c < 4; c++) acc[mi][ni][c] = 0.f;

    const int T = K / GBK;

    auto issue = [&](int kt, int buf) {
        const __nv_bfloat16* Ab = A + (size_t)m0 * K + kt * GBK;
#pragma unroll
        for (int i = 0; i < 2; i++) {
            int fi = t + i * 256;
            int row = fi >> 2, c16 = fi & 3;
            cp_async16((uint32_t)__cvta_generic_to_shared(&As[(buf * GBM + row) * GSTW + c16 * 4]),
                       Ab + (size_t)row * K + c16 * 8);
        }
        const __nv_bfloat16* Bb = B + (size_t)n0 * K + kt * GBK;
        {
            int row = t >> 2, c16 = t & 3;
            cp_async16((uint32_t)__cvta_generic_to_shared(&Bs[(buf * GBN + row) * GSTW + c16 * 4]),
                       Bb + (size_t)row * K + c16 * 8);
        }
        cp_commit();
    };

    issue(0, 0);
    if (T > 1) issue(1, 1);
    if (T > 2) issue(2, 2);

    for (int i = 0; i < T; i++) {
        if (i + 2 < T) cp_wait<2>();
        else if (i + 1 < T) cp_wait<1>();
        else cp_wait<0>();
        __syncthreads();

        const uint32_t* Ab = As + (i % 3) * GBM * GSTW;
        const uint32_t* Bb = Bs + (i % 3) * GBN * GSTW;
#pragma unroll
        for (int ks = 0; ks < 2; ks++) {
            const int kw = ks * 8;
            uint32_t a[2][4];
#pragma unroll
            for (int mi = 0; mi < 2; mi++) {
                int r0 = wm + mi * 16 + g;
                a[mi][0] = Ab[r0 * GSTW + kw + tq];
                a[mi][1] = Ab[(r0 + 8) * GSTW + kw + tq];
                a[mi][2] = Ab[r0 * GSTW + kw + tq + 4];
                a[mi][3] = Ab[(r0 + 8) * GSTW + kw + tq + 4];
            }
#pragma unroll
            for (int ni = 0; ni < 4; ni++) {
                int bc = wn + ni * 8 + g;
                uint32_t b0 = Bb[bc * GSTW + kw + tq];
                uint32_t b1 = Bb[bc * GSTW + kw + tq + 4];
#pragma unroll
                for (int mi = 0; mi < 2; mi++)
                    mma_bf16(acc[mi][ni][0], acc[mi][ni][1], acc[mi][ni][2], acc[mi][ni][3],
                             a[mi][0], a[mi][1], a[mi][2], a[mi][3], b0, b1);
            }
        }
        __syncthreads();
        if (i + 3 < T) issue(i + 3, (i + 3) % 3);
    }

#pragma unroll
    for (int mi = 0; mi < 2; mi++) {
#pragma unroll
        for (int ni = 0; ni < 4; ni++) {
            int col = n0 + wn + ni * 8 + 2 * tq;
            int r0 = m0 + wm + mi * 16 + g;
            int r1 = r0 + 8;
            float bx = bias[col], by = bias[col + 1];
            *(uint32_t*)&C[(size_t)r0 * N + col] = pack_bf16x2(acc[mi][ni][0] + bx, acc[mi][ni][1] + by);
            *(uint32_t*)&C[(size_t)r1 * N + col] = pack_bf16x2(acc[mi][ni][2] + bx, acc[mi][ni][3] + by);
        }
    }
}

// ====== fused GEMM2 + bias + residual + LayerNorm ===========================
// out = LN(resid + A @ B^T + bias). Block tile 16x256 (full rows, grid=256),
// 8 warps each 16x32. Depth-3 cp.async pipeline; resid/bias/gamma/beta
// prefetched into smem during the mainloop -> pure-smem epilogue.
#define G2BM 16
#define G2BN 256
#define G2AB (3 * G2BM * GSTW + 3 * G2BN * GSTW)      // 16320 words
#define G2RES G2AB                                     // resid: 4096 words
#define G2PAR (G2AB + G2BM * 256)                      // bias|gamma|beta: 768
#define G2WORDS (G2PAR + 768)                          // total 21184 words

__global__ void gemm2_ln_kernel(const __nv_bfloat16* __restrict__ A,
                                const __nv_bfloat16* __restrict__ B,
                                const float* __restrict__ bias,
                                const float* __restrict__ resid,
                                const float* __restrict__ gamma,
                                const float* __restrict__ beta,
                                float* __restrict__ out) {
    extern __shared__ uint32_t sm[];
    uint32_t* As = sm;                      // [3][G2BM][GSTW]
    uint32_t* Bs = sm + 3 * G2BM * GSTW;    // [3][G2BN][GSTW]
    float* Rs = (float*)(sm + G2RES);       // [16][256] residual
    float* Pv = (float*)(sm + G2PAR);       // bias[256] gamma[256] beta[256]
    float* Cs = (float*)sm;                 // epilogue alias, stride 264

    const int t = threadIdx.x;              // 256 threads
    const int wid = t >> 5;
    const int lane = t & 31;
    const int g = lane >> 2;
    const int tq = lane & 3;
    const int wn = wid * 32;
    const int m0 = blockIdx.x * G2BM;
    const int K = 256, T = 8;

    float acc[4][4];
#pragma unroll
    for (int ni = 0; ni < 4; ni++)
#pragma unroll
        for (int c = 0; c < 4; c++) acc[ni][c] = 0.f;

    auto issue = [&](int kt, int buf) {
        if (t < 64) {                       // A: 16 rows x 4 chunks
            int row = t >> 2, c16 = t & 3;
            cp_async16((uint32_t)__cvta_generic_to_shared(&As[(buf * G2BM + row) * GSTW + c16 * 4]),
                       A + (size_t)(m0 + row) * K + kt * GBK + c16 * 8);
        }
#pragma unroll
        for (int i = 0; i < 4; i++) {       // B: 256 rows x 4 chunks
            int fi = t + i * 256;
            int row = fi >> 2, c16 = fi & 3;
            cp_async16((uint32_t)__cvta_generic_to_shared(&Bs[(buf * G2BN + row) * GSTW + c16 * 4]),
                       B + (size_t)row * K + kt * GBK + c16 * 8);
        }
        // resid rows [kt*2, kt*2+2): 2 rows x 64 chunks (threads 0..127)
        if (t < 128) {
            int rr = kt * 2 + (t >> 6);
            int c4 = t & 63;
            cp_async16((uint32_t)__cvta_generic_to_shared(&Rs[rr * 256 + c4 * 4]),
                       resid + (size_t)(m0 + rr) * 256 + c4 * 4);
        }
        if (kt == 0) {                      // params: 192 chunks
            if (t < 64)
                cp_async16((uint32_t)__cvta_generic_to_shared(&Pv[t * 4]), bias + t * 4);
            else if (t < 128)
                cp_async16((uint32_t)__cvta_generic_to_shared(&Pv[256 + (t - 64) * 4]), gamma + (t - 64) * 4);
            else if (t < 192)
                cp_async16((uint32_t)__cvta_generic_to_shared(&Pv[512 + (t - 128) * 4]), beta + (t - 128) * 4);
        }
        cp_commit();
    };

    issue(0, 0);
    issue(1, 1);
    issue(2, 2);

    for (int i = 0; i < T; i++) {
        if (i + 2 < T) cp_wait<2>();
        else if (i + 1 < T) cp_wait<1>();
        else cp_wait<0>();
        __syncthreads();

        const uint32_t* Ab = As + (i % 3) * G2BM * GSTW;
        const uint32_t* Bb = Bs + (i % 3) * G2BN * GSTW;
#pragma unroll
        for (int ks = 0; ks < 2; ks++) {
            const int kw = ks * 8;
            uint32_t a0 = Ab[g * GSTW + kw + tq];
            uint32_t a1 = Ab[(g + 8) * GSTW + kw + tq];
            uint32_t a2 = Ab[g * GSTW + kw + tq + 4];
            uint32_t a3 = Ab[(g + 8) * GSTW + kw + tq + 4];
#pragma unroll
            for (int ni = 0; ni < 4; ni++) {
                int bc = wn + ni * 8 + g;
                uint32_t b0 = Bb[bc * GSTW + kw + tq];
                uint32_t b1 = Bb[bc * GSTW + kw + tq + 4];
                mma_bf16(acc[ni][0], acc[ni][1], acc[ni][2], acc[ni][3],
                         a0, a1, a2, a3, b0, b1);
            }
        }
        __syncthreads();
        if (i + 3 < T) issue(i + 3, (i + 3) % 3);
    }

    // stage acc + bias into smem (full 256-wide rows; aliases AB buffers)
#pragma unroll
    for (int ni = 0; ni < 4; ni++) {
        int col = wn + ni * 8 + 2 * tq;
        float bx = Pv[col], by = Pv[col + 1];
        *(float2*)&Cs[g * 264 + col] = make_float2(acc[ni][0] + bx, acc[ni][1] + by);
        *(float2*)&Cs[(g + 8) * 264 + col] = make_float2(acc[ni][2] + bx, acc[ni][3] + by);
    }
    __syncthreads();

    // LayerNorm: warp w handles rows 2w, 2w+1; all operands in smem
#pragma unroll
    for (int rr = wid * 2; rr < wid * 2 + 2; rr++) {
        float v[8], s = 0.f;
#pragma unroll
        for (int k = 0; k < 8; k++) {
            int c = lane + 32 * k;
            v[k] = Cs[rr * 264 + c] + Rs[rr * 256 + c];
            s += v[k];
        }
#pragma unroll
        for (int o = 16; o > 0; o >>= 1) s += __shfl_xor_sync(0xffffffffu, s, o);
        const float mean = s * (1.f / 256.f);
        float sq = 0.f;
#pragma unroll
        for (int k = 0; k < 8; k++) { float d = v[k] - mean; sq += d * d; }
#pragma unroll
        for (int o = 16; o > 0; o >>= 1) sq += __shfl_xor_sync(0xffffffffu, sq, o);
        const float rsig = rsqrtf(sq * (1.f / 256.f) + 1e-5f);
#pragma unroll
        for (int k = 0; k < 8; k++) {
            int c = lane + 32 * k;
            out[(size_t)(m0 + rr) * 256 + c] = (v[k] - mean) * rsig * Pv[256 + c] + Pv[512 + c];
        }
    }
}

// ============== bf16 mma flash attention, block-diagonal mask ===============
// 4 warps; warp w owns query rows [16w,16w+16). cp.async double-buffered K/V;
// V^T fragments via ldmatrix.trans (no scalar transpose stores).
#define QT 64
#define KT 64
#define QSTW 20   // Qs/Ks/Vs word stride (32 bf16 = 16 words + 4 pad)
#define PSTW 36   // Pp word stride

__device__ __forceinline__ int lb_search(const int* __restrict__ a, int n, int v) {
    int lo = 0, hi = n;
    while (lo < hi) { int mid = (lo + hi) >> 1; if (a[mid] < v) lo = mid + 1; else hi = mid; }
    return lo;
}
__device__ __forceinline__ int ub_search(const int* __restrict__ a, int n, int v) {
    int lo = 0, hi = n;
    while (lo < hi) { int mid = (lo + hi) >> 1; if (a[mid] <= v) lo = mid + 1; else hi = mid; }
    return lo;
}

__global__ void flash_attn_kernel(const __nv_bfloat16* __restrict__ qkv,
                                  const int* __restrict__ bidx,
                                  __nv_bfloat16* __restrict__ attn_out) {
    __shared__ uint32_t Qs[QT * QSTW];
    __shared__ uint32_t Ks[2][KT * QSTW];
    __shared__ uint32_t Vs[2][KT * QSTW];   // row-major [key][d]
    __shared__ uint32_t Pp[QT * PSTW];
    __shared__ int qb[QT];
    __shared__ int kb[2][KT];

    const int h = blockIdx.y;
    const int q0 = blockIdx.x * QT;
    const int t = threadIdx.x;            // 128 threads
    const int wid = t >> 5;
    const int lane = t & 31;
    const int g = lane >> 2;
    const int tq = lane & 3;
    const int qoff = h * HD;
    const int koff = D_MODEL + h * HD;
    const int voff = 2 * D_MODEL + h * HD;

    // zero K/V buffers once (so tail keys are always finite -> P=0 kills them)
#pragma unroll
    for (int i = t; i < 2 * KT * QSTW; i += 128) {
        ((uint32_t*)Ks)[i] = 0;
        ((uint32_t*)Vs)[i] = 0;
    }
    // load Q tile: 64 rows x 4 uint4-chunks (8 bf16 each)
#pragma unroll
    for (int i = 0; i < 2; i++) {
        int fi = t + i * 128;
        int row = fi >> 2, c = fi & 3;
        *(uint4*)&Qs[row * QSTW + c * 4] =
            *(const uint4*)&qkv[(size_t)(q0 + row) * QKV_W + qoff + c * 8];
    }
    if (t < QT) qb[t] = bidx[q0 + t];
    __syncthreads();   // zero-fill + Q visible before cp.async lands on top

    const int myb0 = qb[wid * 16 + g];
    const int myb1 = qb[wid * 16 + g + 8];
    const int seg_s = lb_search(bidx, N_TOK, qb[0]);
    const int seg_e = ub_search(bidx, N_TOK, qb[QT - 1]);
    const int T = (seg_e - seg_s + KT - 1) / KT;

    auto issue_tile = [&](int k0, int buf) {
        const int kt = min(KT, seg_e - k0);
        // 64 rows x 4 chunks of 16B each for K and V: fi covers 256 chunks,
        // each thread issues 2 K-chunks + 2 V-chunks (full 64-byte rows).
#pragma unroll
        for (int i = 0; i < 2; i++) {
            int fi = t + i * 128;
            int kk = fi >> 2, c = fi & 3;
            if (kk < kt) {
                size_t base = (size_t)(k0 + kk) * QKV_W;
                cp_async16((uint32_t)__cvta_generic_to_shared(&Ks[buf][kk * QSTW + c * 4]),
                           qkv + base + koff + c * 8);
                cp_async16((uint32_t)__cvta_generic_to_shared(&Vs[buf][kk * QSTW + c * 4]),
                           qkv + base + voff + c * 8);
            }
        }
        if (t < KT) kb[buf][t] = (t < kt) ? bidx[k0 + t] : -1;
        cp_commit();
    };

    issue_tile(seg_s, 0);

    // Q fragments (2 k16 steps)
    uint32_t qf[2][4];
#pragma unroll
    for (int ks = 0; ks < 2; ks++) {
        int base = (wid * 16 + g) * QSTW + ks * 8;
        int base8 = (wid * 16 + g + 8) * QSTW + ks * 8;
        qf[ks][0] = Qs[base + tq];
        qf[ks][1] = Qs[base8 + tq];
        qf[ks][2] = Qs[base + tq + 4];
        qf[ks][3] = Qs[base8 + tq + 4];
    }

    const float scale = 0.1767766952966369f; // 1/sqrt(32)
    float m0 = 0.f, m1 = 0.f, l0 = 0.f, l1 = 0.f;  // max init 0 (valid upper bound)
    float oacc[4][4];
#pragma unroll
    for (int nt = 0; nt < 4; nt++)
#pragma unroll
        for (int c = 0; c < 4; c++) oacc[nt][c] = 0.f;

    for (int i = 0; i < T; i++) {
        const int cur = i & 1;
        if (i > 0) __syncthreads();        // all warps done with buffer (i+1)&1
        if (i + 1 < T) issue_tile(seg_s + (i + 1) * KT, cur ^ 1);
        if (i + 1 < T) cp_wait<1>(); else cp_wait<0>();
        __syncthreads();                   // tile i data + kb visible

        const uint32_t* Kc = Ks[cur];
        const int* kbc = kb[cur];
        const uint32_t vsbase = (uint32_t)__cvta_generic_to_shared(&Vs[cur][0]);

        // ---- S = Q K^T: 2 k16 steps x 8 n-tiles ----
        float sacc[8][4];
#pragma unroll
        for (int nt = 0; nt < 8; nt++)
#pragma unroll
            for (int c = 0; c < 4; c++) sacc[nt][c] = 0.f;
#pragma unroll
        for (int ks = 0; ks < 2; ks++) {
            const int kw = ks * 8;
#pragma unroll
            for (int nt = 0; nt < 8; nt++) {
                int kr = (nt * 8 + g) * QSTW + kw;
                mma_bf16(sacc[nt][0], sacc[nt][1], sacc[nt][2], sacc[nt][3],
                         qf[ks][0], qf[ks][1], qf[ks][2], qf[ks][3],
                         Kc[kr + tq], Kc[kr + tq + 4]);
            }
        }

        // ---- mask + row max ----
        float rmax0 = -1e30f, rmax1 = -1e30f;
#pragma unroll
        for (int nt = 0; nt < 8; nt++) {
            int c0 = nt * 8 + 2 * tq;
            int kb0 = kbc[c0], kb1 = kbc[c0 + 1];
            float s0 = (kb0 == myb0) ? sacc[nt][0] * scale : -1e30f;
            float s1 = (kb1 == myb0) ? sacc[nt][1] * scale : -1e30f;
            float s2 = (kb0 == myb1) ? sacc[nt][2] * scale : -1e30f;
            float s3 = (kb1 == myb1) ? sacc[nt][3] * scale : -1e30f;
            sacc[nt][0] = s0; sacc[nt][1] = s1; sacc[nt][2] = s2; sacc[nt][3] = s3;
            rmax0 = fmaxf(rmax0, fmaxf(s0, s1));
            rmax1 = fmaxf(rmax1, fmaxf(s2, s3));
        }
        rmax0 = fmaxf(rmax0, __shfl_xor_sync(0xffffffffu, rmax0, 1));
        rmax0 = fmaxf(rmax0, __shfl_xor_sync(0xffffffffu, rmax0, 2));
        rmax1 = fmaxf(rmax1, __shfl_xor_sync(0xffffffffu, rmax1, 1));
        rmax1 = fmaxf(rmax1, __shfl_xor_sync(0xffffffffu, rmax1, 2));
        const float mn0 = fmaxf(m0, rmax0);
        const float mn1 = fmaxf(m1, rmax1);
        const float al0 = __expf(m0 - mn0);
        const float al1 = __expf(m1 - mn1);
        m0 = mn0; m1 = mn1;

        // ---- exp, pack P to bf16 pairs, update l ----
        float ls0 = 0.f, ls1 = 0.f;
        const int pr0 = (wid * 16 + g) * PSTW;
        const int pr1 = (wid * 16 + g + 8) * PSTW;
#pragma unroll
        for (int nt = 0; nt < 8; nt++) {
            float p0 = __expf(sacc[nt][0] - mn0);
            float p1 = __expf(sacc[nt][1] - mn0);
            float p2 = __expf(sacc[nt][2] - mn1);
            float p3 = __expf(sacc[nt][3] - mn1);
            ls0 += p0 + p1;
            ls1 += p2 + p3;
            Pp[pr0 + nt * 4 + tq] = pack_bf16x2(p0, p1);
            Pp[pr1 + nt * 4 + tq] = pack_bf16x2(p2, p3);
        }
        ls0 += __shfl_xor_sync(0xffffffffu, ls0, 1);
        ls0 += __shfl_xor_sync(0xffffffffu, ls0, 2);
        ls1 += __shfl_xor_sync(0xffffffffu, ls1, 1);
        ls1 += __shfl_xor_sync(0xffffffffu, ls1, 2);
        l0 = l0 * al0 + ls0;
        l1 = l1 * al1 + ls1;
#pragma unroll
        for (int nt = 0; nt < 4; nt++) {
            oacc[nt][0] *= al0; oacc[nt][1] *= al0;
            oacc[nt][2] *= al1; oacc[nt][3] *= al1;
        }
        __syncwarp();  // warp-local P rows visible

        // ---- O += P V: ldmatrix.trans V fragments; 2 key-halves x 2 k16 ----
#pragma unroll
        for (int half = 0; half < 2; half++) {
            const int key0 = half * 32;
            uint32_t vb[4][4];  // [d-block nt][key octet 0..3 within half]
#pragma unroll
            for (int nt = 0; nt < 4; nt++) {
                uint32_t addr = vsbase + ((key0 + lane) * QSTW + nt * 4) * 4;
                ldsm_x4_trans(vb[nt][0], vb[nt][1], vb[nt][2], vb[nt][3], addr);
            }
#pragma unroll
            for (int ks = 0; ks < 2; ks++) {
                const int kw = (half * 2 + ks) * 8;
                uint32_t a0 = Pp[pr0 + kw + tq];
                uint32_t a1 = Pp[pr1 + kw + tq];
                uint32_t a2 = Pp[pr0 + kw + tq + 4];
                uint32_t a3 = Pp[pr1 + kw + tq + 4];
#pragma unroll
                for (int nt = 0; nt < 4; nt++)
                    mma_bf16(oacc[nt][0], oacc[nt][1], oacc[nt][2], oacc[nt][3],
                             a0, a1, a2, a3, vb[nt][ks * 2], vb[nt][ks * 2 + 1]);
            }
        }
    }

    const float i0 = 1.f / l0;
    const float i1 = 1.f / l1;
    const int r0 = q0 + wid * 16 + g;
    const int r1 = r0 + 8;
#pragma unroll
    for (int nt = 0; nt < 4; nt++) {
        int col = h * HD + nt * 8 + 2 * tq;
        *(uint32_t*)&attn_out[(size_t)r0 * D_MODEL + col] = pack_bf16x2(oacc[nt][0] * i0, oacc[nt][1] * i0);
        *(uint32_t*)&attn_out[(size_t)r1 * D_MODEL + col] = pack_bf16x2(oacc[nt][2] * i1, oacc[nt][3] * i1);
    }
}

// ---------------- launch ----------------------------------------------------
extern "C" void kernel_launch(void* const* d_in, const int* in_sizes, int n_in,
                              void* d_out, int out_size) {
    const float* slots    = (const float*)d_in[0];
    const int*   batch_ix = (const int*)d_in[1];
    const float* w_in     = (const float*)d_in[2];
    const float* b_in     = (const float*)d_in[3];
    const float* w_out    = (const float*)d_in[4];
    const float* b_out    = (const float*)d_in[5];
    const float* ln_gamma = (const float*)d_in[6];
    const float* ln_beta  = (const float*)d_in[7];
    float* out = (float*)d_out;

    __nv_bfloat16* qkv_bf;   cudaGetSymbolAddress((void**)&qkv_bf,   g_qkv_bf);
    __nv_bfloat16* attn_bf;  cudaGetSymbolAddress((void**)&attn_bf,  g_attn_bf);
    __nv_bfloat16* slots_bf; cudaGetSymbolAddress((void**)&slots_bf, g_slots_bf);
    __nv_bfloat16* win_bf;   cudaGetSymbolAddress((void**)&win_bf,   g_win_bf);
    __nv_bfloat16* wout_bf;  cudaGetSymbolAddress((void**)&wout_bf,  g_wout_bf);

    // 0) convert inputs to bf16 (slots, w_in, w_out)
    {
        const int n0 = N_TOK * D_MODEL, n1 = QKV_W * D_MODEL, n2 = D_MODEL * D_MODEL;
        const int total4 = (n0 + n1 + n2) / 4;
        cvt_bf16_kernel<<<(total4 + 255) / 256, 256>>>(slots, slots_bf, n0,
                                                       w_in, win_bf, n1,
                                                       w_out, wout_bf, n2);
    }
    // 1) QKV projection (bf16 in/out): qkv = slots @ w_in^T + b_in
    {
        dim3 grid(QKV_W / GBN, N_TOK / GBM);
        gemm_bf16_kernel<<<grid, 256>>>(slots_bf, win_bf, b_in, qkv_bf,
                                        N_TOK, QKV_W, D_MODEL);
    }
    // 2) block-diagonal flash attention (bf16 mma, pipelined K/V)
    {
        dim3 grid(N_TOK / QT, H_HEADS);
        flash_attn_kernel<<<grid, 128>>>(qkv_bf, batch_ix, attn_bf);
    }
    // 3) fused out-projection + bias + residual + LayerNorm (dynamic smem)
    {
        const int smem_bytes = G2WORDS * (int)sizeof(uint32_t);  // ~85 KB
        cudaFuncSetAttribute(gemm2_ln_kernel,
                             cudaFuncAttributeMaxDynamicSharedMemorySize, smem_bytes);
        gemm2_ln_kernel<<<N_TOK / G2BM, 256, smem_bytes>>>(attn_bf, wout_bf, b_out, slots,
                                                           ln_gamma, ln_beta, out);
    }
}

// round 12
// speedup vs baseline: 5.4008x; 1.0231x over previous
#include <cuda_runtime.h>
#include <cuda_bf16.h>
#include <math.h>
#include <stdint.h>

#define N_TOK 4096
#define D_MODEL 256
#define H_HEADS 8
#define HD 32
#define QKV_W 768

// ---------------- scratch (device globals; no allocation allowed) ----------
__device__ __nv_bfloat16 g_qkv_bf[N_TOK * QKV_W];      // bf16 q|k|v
__device__ __nv_bfloat16 g_attn_bf[N_TOK * D_MODEL];   // attention out (bf16)
__device__ __nv_bfloat16 g_slots_bf[N_TOK * D_MODEL];
__device__ __nv_bfloat16 g_win_bf[QKV_W * D_MODEL];
__device__ __nv_bfloat16 g_wout_bf[D_MODEL * D_MODEL];

// =================== mma / cp.async / ldmatrix helpers =====================
__device__ __forceinline__ void mma_bf16(float& d0, float& d1, float& d2, float& d3,
                                         uint32_t a0, uint32_t a1, uint32_t a2, uint32_t a3,
                                         uint32_t b0, uint32_t b1) {
    asm volatile("mma.sync.aligned.m16n8k16.row.col.f32.bf16.bf16.f32 "
                 "{%0,%1,%2,%3}, {%4,%5,%6,%7}, {%8,%9}, {%0,%1,%2,%3};"
                 : "+f"(d0), "+f"(d1), "+f"(d2), "+f"(d3)
                 : "r"(a0), "r"(a1), "r"(a2), "r"(a3), "r"(b0), "r"(b1));
}

__device__ __forceinline__ void cp_async16(uint32_t dst, const void* src) {
    asm volatile("cp.async.cg.shared.global [%0], [%1], 16;" :: "r"(dst), "l"(src));
}
__device__ __forceinline__ void cp_commit() {
    asm volatile("cp.async.commit_group;");
}
template <int Nwait>
__device__ __forceinline__ void cp_wait() {
    asm volatile("cp.async.wait_group %0;" :: "n"(Nwait));
}

// transposed 8x8 b16 x4 loads (for V^T fragments)
__device__ __forceinline__ void ldsm_x4_trans(uint32_t& r0, uint32_t& r1,
                                              uint32_t& r2, uint32_t& r3, uint32_t addr) {
    asm volatile("ldmatrix.sync.aligned.m8n8.x4.trans.shared.b16 {%0,%1,%2,%3}, [%4];"
                 : "=r"(r0), "=r"(r1), "=r"(r2), "=r"(r3) : "r"(addr));
}

// pack two fp32 into one bf16x2 register (lo -> low half, hi -> high half)
__device__ __forceinline__ uint32_t pack_bf16x2(float lo, float hi) {
    uint32_t r;
    asm("cvt.rn.bf16x2.f32 %0, %1, %2;" : "=r"(r) : "f"(hi), "f"(lo));
    return r;
}

// =================== fp32 -> bf16 conversion (3 arrays, one launch) ========
__global__ void cvt_bf16_kernel(const float* __restrict__ s0, __nv_bfloat16* __restrict__ d0, int n0,
                                const float* __restrict__ s1, __nv_bfloat16* __restrict__ d1, int n1,
                                const float* __restrict__ s2, __nv_bfloat16* __restrict__ d2, int n2) {
    int i = blockIdx.x * blockDim.x + threadIdx.x;  // one float4 per thread
    const float* s;
    __nv_bfloat16* d;
    int off;
    int q0 = n0 >> 2, q1 = q0 + (n1 >> 2), q2 = q1 + (n2 >> 2);
    if (i >= q2) return;
    if (i < q0) { s = s0; d = d0; off = i * 4; }
    else if (i < q1) { s = s1; d = d1; off = (i - q0) * 4; }
    else { s = s2; d = d2; off = (i - q1) * 4; }
    float4 v = *(const float4*)&s[off];
    *(uint32_t*)&d[off] = pack_bf16x2(v.x, v.y);
    *(uint32_t*)&d[off + 2] = pack_bf16x2(v.z, v.w);
}

// ===== bf16 GEMM1: C[M,N] = A[M,K] @ B[N,K]^T + bias, bf16 output ==========
#define GBM 128
#define GBN 64
#define GBK 32
#define GSTW 20

__global__ void gemm_bf16_kernel(const __nv_bfloat16* __restrict__ A,
                                 const __nv_bfloat16* __restrict__ B,
                                 const float* __restrict__ bias,
                                 __nv_bfloat16* __restrict__ C,
                                 int M, int N, int K) {
    __shared__ uint32_t As[3 * GBM * GSTW];
    __shared__ uint32_t Bs[3 * GBN * GSTW];

    const int t = threadIdx.x;            // 256 threads
    const int wid = t >> 5;
    const int lane = t & 31;
    const int g = lane >> 2;
    const int tq = lane & 3;
    const int wm = (wid & 3) * 32;
    const int wn = (wid >> 2) * 32;
    const int m0 = blockIdx.y * GBM;
    const int n0 = blockIdx.x * GBN;

    float acc[2][4][4];
#pragma unroll
    for (int mi = 0; mi < 2; mi++)
#pragma unroll
        for (int ni = 0; ni < 4; ni++)
#pragma unroll
            for (int c = 0; c < 4; c++) acc[mi][ni][c] = 0.f;

    const int T = K / GBK;

    auto issue = [&](int kt, int buf) {
        const __nv_bfloat16* Ab = A + (size_t)m0 * K + kt * GBK;
#pragma unroll
        for (int i = 0; i < 2; i++) {
            int fi = t + i * 256;
            int row = fi >> 2, c16 = fi & 3;
            cp_async16((uint32_t)__cvta_generic_to_shared(&As[(buf * GBM + row) * GSTW + c16 * 4]),
                       Ab + (size_t)row * K + c16 * 8);
        }
        const __nv_bfloat16* Bb = B + (size_t)n0 * K + kt * GBK;
        {
            int row = t >> 2, c16 = t & 3;
            cp_async16((uint32_t)__cvta_generic_to_shared(&Bs[(buf * GBN + row) * GSTW + c16 * 4]),
                       Bb + (size_t)row * K + c16 * 8);
        }
        cp_commit();
    };

    issue(0, 0);
    if (T > 1) issue(1, 1);
    if (T > 2) issue(2, 2);

    for (int i = 0; i < T; i++) {
        if (i + 2 < T) cp_wait<2>();
        else if (i + 1 < T) cp_wait<1>();
        else cp_wait<0>();
        __syncthreads();

        const uint32_t* Ab = As + (i % 3) * GBM * GSTW;
        const uint32_t* Bb = Bs + (i % 3) * GBN * GSTW;
#pragma unroll
        for (int ks = 0; ks < 2; ks++) {
            const int kw = ks * 8;
            uint32_t a[2][4];
#pragma unroll
            for (int mi = 0; mi < 2; mi++) {
                int r0 = wm + mi * 16 + g;
                a[mi][0] = Ab[r0 * GSTW + kw + tq];
                a[mi][1] = Ab[(r0 + 8) * GSTW + kw + tq];
                a[mi][2] = Ab[r0 * GSTW + kw + tq + 4];
                a[mi][3] = Ab[(r0 + 8) * GSTW + kw + tq + 4];
            }
#pragma unroll
            for (int ni = 0; ni < 4; ni++) {
                int bc = wn + ni * 8 + g;
                uint32_t b0 = Bb[bc * GSTW + kw + tq];
                uint32_t b1 = Bb[bc * GSTW + kw + tq + 4];
#pragma unroll
                for (int mi = 0; mi < 2; mi++)
                    mma_bf16(acc[mi][ni][0], acc[mi][ni][1], acc[mi][ni][2], acc[mi][ni][3],
                             a[mi][0], a[mi][1], a[mi][2], a[mi][3], b0, b1);
            }
        }
        __syncthreads();
        if (i + 3 < T) issue(i + 3, (i + 3) % 3);
    }

#pragma unroll
    for (int mi = 0; mi < 2; mi++) {
#pragma unroll
        for (int ni = 0; ni < 4; ni++) {
            int col = n0 + wn + ni * 8 + 2 * tq;
            int r0 = m0 + wm + mi * 16 + g;
            int r1 = r0 + 8;
            float bx = bias[col], by = bias[col + 1];
            *(uint32_t*)&C[(size_t)r0 * N + col] = pack_bf16x2(acc[mi][ni][0] + bx, acc[mi][ni][1] + by);
            *(uint32_t*)&C[(size_t)r1 * N + col] = pack_bf16x2(acc[mi][ni][2] + bx, acc[mi][ni][3] + by);
        }
    }
}

// ====== fused GEMM2 + bias + residual + LayerNorm ===========================
// out = LN(resid + A @ B^T + bias). Block tile 32x256 (grid=128), 512 threads
// (16 warps, 2m x 8n, warp tile 16x32). Depth-3 cp.async pipeline;
// resid/bias/gamma/beta prefetched into smem -> pure-smem epilogue.
#define G2BM 32
#define G2BN 256
#define G2AB (3 * G2BM * GSTW + 3 * G2BN * GSTW)      // 17280 words
#define G2RES G2AB                                     // resid: 8192 words
#define G2PAR (G2AB + G2BM * 256)                      // bias|gamma|beta: 768
#define G2WORDS (G2PAR + 768)                          // total 26240 words (~103 KB)

__global__ void gemm2_ln_kernel(const __nv_bfloat16* __restrict__ A,
                                const __nv_bfloat16* __restrict__ B,
                                const float* __restrict__ bias,
                                const float* __restrict__ resid,
                                const float* __restrict__ gamma,
                                const float* __restrict__ beta,
                                float* __restrict__ out) {
    extern __shared__ uint32_t sm[];
    uint32_t* As = sm;                      // [3][G2BM][GSTW]
    uint32_t* Bs = sm + 3 * G2BM * GSTW;    // [3][G2BN][GSTW]
    float* Rs = (float*)(sm + G2RES);       // [32][256] residual
    float* Pv = (float*)(sm + G2PAR);       // bias[256] gamma[256] beta[256]
    float* Cs = (float*)sm;                 // epilogue alias, stride 264

    const int t = threadIdx.x;              // 512 threads
    const int wid = t >> 5;                 // 0..15
    const int lane = t & 31;
    const int g = lane >> 2;
    const int tq = lane & 3;
    const int wm = (wid & 1) * 16;
    const int wn = (wid >> 1) * 32;
    const int m0 = blockIdx.x * G2BM;
    const int K = 256, T = 8;

    float acc[4][4];
#pragma unroll
    for (int ni = 0; ni < 4; ni++)
#pragma unroll
        for (int c = 0; c < 4; c++) acc[ni][c] = 0.f;

    auto issue = [&](int kt, int buf) {
        if (t < 128) {                      // A: 32 rows x 4 chunks
            int row = t >> 2, c16 = t & 3;
            cp_async16((uint32_t)__cvta_generic_to_shared(&As[(buf * G2BM + row) * GSTW + c16 * 4]),
                       A + (size_t)(m0 + row) * K + kt * GBK + c16 * 8);
        }
#pragma unroll
        for (int i = 0; i < 2; i++) {       // B: 256 rows x 4 chunks = 1024
            int fi = t + i * 512;
            int row = fi >> 2, c16 = fi & 3;
            cp_async16((uint32_t)__cvta_generic_to_shared(&Bs[(buf * G2BN + row) * GSTW + c16 * 4]),
                       B + (size_t)row * K + kt * GBK + c16 * 8);
        }
        // resid rows [kt*4, kt*4+4): 4 rows x 64 chunks (threads 0..255)
        if (t < 256) {
            int rr = kt * 4 + (t >> 6);
            int c4 = t & 63;
            cp_async16((uint32_t)__cvta_generic_to_shared(&Rs[rr * 256 + c4 * 4]),
                       resid + (size_t)(m0 + rr) * 256 + c4 * 4);
        }
        if (kt == 0) {                      // params: 192 chunks
            if (t < 64)
                cp_async16((uint32_t)__cvta_generic_to_shared(&Pv[t * 4]), bias + t * 4);
            else if (t < 128)
                cp_async16((uint32_t)__cvta_generic_to_shared(&Pv[256 + (t - 64) * 4]), gamma + (t - 64) * 4);
            else if (t < 192)
                cp_async16((uint32_t)__cvta_generic_to_shared(&Pv[512 + (t - 128) * 4]), beta + (t - 128) * 4);
        }
        cp_commit();
    };

    issue(0, 0);
    issue(1, 1);
    issue(2, 2);

    for (int i = 0; i < T; i++) {
        if (i + 2 < T) cp_wait<2>();
        else if (i + 1 < T) cp_wait<1>();
        else cp_wait<0>();
        __syncthreads();

        const uint32_t* Ab = As + (i % 3) * G2BM * GSTW;
        const uint32_t* Bb = Bs + (i % 3) * G2BN * GSTW;
#pragma unroll
        for (int ks = 0; ks < 2; ks++) {
            const int kw = ks * 8;
            uint32_t a0 = Ab[(wm + g) * GSTW + kw + tq];
            uint32_t a1 = Ab[(wm + g + 8) * GSTW + kw + tq];
            uint32_t a2 = Ab[(wm + g) * GSTW + kw + tq + 4];
            uint32_t a3 = Ab[(wm + g + 8) * GSTW + kw + tq + 4];
#pragma unroll
            for (int ni = 0; ni < 4; ni++) {
                int bc = wn + ni * 8 + g;
                uint32_t b0 = Bb[bc * GSTW + kw + tq];
                uint32_t b1 = Bb[bc * GSTW + kw + tq + 4];
                mma_bf16(acc[ni][0], acc[ni][1], acc[ni][2], acc[ni][3],
                         a0, a1, a2, a3, b0, b1);
            }
        }
        __syncthreads();
        if (i + 3 < T) issue(i + 3, (i + 3) % 3);
    }

    // stage acc + bias into smem (full 256-wide rows; aliases AB buffers)
#pragma unroll
    for (int ni = 0; ni < 4; ni++) {
        int col = wn + ni * 8 + 2 * tq;
        float bx = Pv[col], by = Pv[col + 1];
        *(float2*)&Cs[(wm + g) * 264 + col] = make_float2(acc[ni][0] + bx, acc[ni][1] + by);
        *(float2*)&Cs[(wm + g + 8) * 264 + col] = make_float2(acc[ni][2] + bx, acc[ni][3] + by);
    }
    __syncthreads();

    // LayerNorm: warp w handles rows 2w, 2w+1; all operands in smem
#pragma unroll
    for (int rr = wid * 2; rr < wid * 2 + 2; rr++) {
        float v[8], s = 0.f;
#pragma unroll
        for (int k = 0; k < 8; k++) {
            int c = lane + 32 * k;
            v[k] = Cs[rr * 264 + c] + Rs[rr * 256 + c];
            s += v[k];
        }
#pragma unroll
        for (int o = 16; o > 0; o >>= 1) s += __shfl_xor_sync(0xffffffffu, s, o);
        const float mean = s * (1.f / 256.f);
        float sq = 0.f;
#pragma unroll
        for (int k = 0; k < 8; k++) { float d = v[k] - mean; sq += d * d; }
#pragma unroll
        for (int o = 16; o > 0; o >>= 1) sq += __shfl_xor_sync(0xffffffffu, sq, o);
        const float rsig = rsqrtf(sq * (1.f / 256.f) + 1e-5f);
#pragma unroll
        for (int k = 0; k < 8; k++) {
            int c = lane + 32 * k;
            out[(size_t)(m0 + rr) * 256 + c] = (v[k] - mean) * rsig * Pv[256 + c] + Pv[512 + c];
        }
    }
}

// ============== bf16 mma flash attention, block-diagonal mask ===============
// 4 warps; warp w owns query rows [16w,16w+16). cp.async double-buffered K/V;
// V^T fragments via ldmatrix.trans (no scalar transpose stores).
#define QT 64
#define KT 64
#define QSTW 20   // Qs/Ks/Vs word stride (32 bf16 = 16 words + 4 pad)
#define PSTW 36   // Pp word stride

__device__ __forceinline__ int lb_search(const int* __restrict__ a, int n, int v) {
    int lo = 0, hi = n;
    while (lo < hi) { int mid = (lo + hi) >> 1; if (a[mid] < v) lo = mid + 1; else hi = mid; }
    return lo;
}
__device__ __forceinline__ int ub_search(const int* __restrict__ a, int n, int v) {
    int lo = 0, hi = n;
    while (lo < hi) { int mid = (lo + hi) >> 1; if (a[mid] <= v) lo = mid + 1; else hi = mid; }
    return lo;
}

__global__ void flash_attn_kernel(const __nv_bfloat16* __restrict__ qkv,
                                  const int* __restrict__ bidx,
                                  __nv_bfloat16* __restrict__ attn_out) {
    __shared__ uint32_t Qs[QT * QSTW];
    __shared__ uint32_t Ks[2][KT * QSTW];
    __shared__ uint32_t Vs[2][KT * QSTW];   // row-major [key][d]
    __shared__ uint32_t Pp[QT * PSTW];
    __shared__ int qb[QT];
    __shared__ int kb[2][KT];

    const int h = blockIdx.y;
    const int q0 = blockIdx.x * QT;
    const int t = threadIdx.x;            // 128 threads
    const int wid = t >> 5;
    const int lane = t & 31;
    const int g = lane >> 2;
    const int tq = lane & 3;
    const int qoff = h * HD;
    const int koff = D_MODEL + h * HD;
    const int voff = 2 * D_MODEL + h * HD;

    // zero K/V buffers once (so tail keys are always finite -> P=0 kills them)
#pragma unroll
    for (int i = t; i < 2 * KT * QSTW; i += 128) {
        ((uint32_t*)Ks)[i] = 0;
        ((uint32_t*)Vs)[i] = 0;
    }
    // load Q tile: 64 rows x 4 uint4-chunks (8 bf16 each)
#pragma unroll
    for (int i = 0; i < 2; i++) {
        int fi = t + i * 128;
        int row = fi >> 2, c = fi & 3;
        *(uint4*)&Qs[row * QSTW + c * 4] =
            *(const uint4*)&qkv[(size_t)(q0 + row) * QKV_W + qoff + c * 8];
    }
    if (t < QT) qb[t] = bidx[q0 + t];
    __syncthreads();   // zero-fill + Q visible before cp.async lands on top

    const int myb0 = qb[wid * 16 + g];
    const int myb1 = qb[wid * 16 + g + 8];
    const int seg_s = lb_search(bidx, N_TOK, qb[0]);
    const int seg_e = ub_search(bidx, N_TOK, qb[QT - 1]);
    const int T = (seg_e - seg_s + KT - 1) / KT;

    auto issue_tile = [&](int k0, int buf) {
        const int kt = min(KT, seg_e - k0);
        // 64 rows x 4 chunks of 16B each for K and V: fi covers 256 chunks,
        // each thread issues 2 K-chunks + 2 V-chunks (full 64-byte rows).
#pragma unroll
        for (int i = 0; i < 2; i++) {
            int fi = t + i * 128;
            int kk = fi >> 2, c = fi & 3;
            if (kk < kt) {
                size_t base = (size_t)(k0 + kk) * QKV_W;
                cp_async16((uint32_t)__cvta_generic_to_shared(&Ks[buf][kk * QSTW + c * 4]),
                           qkv + base + koff + c * 8);
                cp_async16((uint32_t)__cvta_generic_to_shared(&Vs[buf][kk * QSTW + c * 4]),
                           qkv + base + voff + c * 8);
            }
        }
        if (t < KT) kb[buf][t] = (t < kt) ? bidx[k0 + t] : -1;
        cp_commit();
    };

    issue_tile(seg_s, 0);

    // Q fragments (2 k16 steps)
    uint32_t qf[2][4];
#pragma unroll
    for (int ks = 0; ks < 2; ks++) {
        int base = (wid * 16 + g) * QSTW + ks * 8;
        int base8 = (wid * 16 + g + 8) * QSTW + ks * 8;
        qf[ks][0] = Qs[base + tq];
        qf[ks][1] = Qs[base8 + tq];
        qf[ks][2] = Qs[base + tq + 4];
        qf[ks][3] = Qs[base8 + tq + 4];
    }

    const float scale = 0.1767766952966369f; // 1/sqrt(32)
    float m0 = 0.f, m1 = 0.f, l0 = 0.f, l1 = 0.f;  // max init 0 (valid upper bound)
    float oacc[4][4];
#pragma unroll
    for (int nt = 0; nt < 4; nt++)
#pragma unroll
        for (int c = 0; c < 4; c++) oacc[nt][c] = 0.f;

    for (int i = 0; i < T; i++) {
        const int cur = i & 1;
        if (i > 0) __syncthreads();        // all warps done with buffer (i+1)&1
        if (i + 1 < T) issue_tile(seg_s + (i + 1) * KT, cur ^ 1);
        if (i + 1 < T) cp_wait<1>(); else cp_wait<0>();
        __syncthreads();                   // tile i data + kb visible

        const uint32_t* Kc = Ks[cur];
        const int* kbc = kb[cur];
        const uint32_t vsbase = (uint32_t)__cvta_generic_to_shared(&Vs[cur][0]);

        // ---- S = Q K^T: 2 k16 steps x 8 n-tiles ----
        float sacc[8][4];
#pragma unroll
        for (int nt = 0; nt < 8; nt++)
#pragma unroll
            for (int c = 0; c < 4; c++) sacc[nt][c] = 0.f;
#pragma unroll
        for (int ks = 0; ks < 2; ks++) {
            const int kw = ks * 8;
#pragma unroll
            for (int nt = 0; nt < 8; nt++) {
                int kr = (nt * 8 + g) * QSTW + kw;
                mma_bf16(sacc[nt][0], sacc[nt][1], sacc[nt][2], sacc[nt][3],
                         qf[ks][0], qf[ks][1], qf[ks][2], qf[ks][3],
                         Kc[kr + tq], Kc[kr + tq + 4]);
            }
        }

        // ---- mask + row max ----
        float rmax0 = -1e30f, rmax1 = -1e30f;
#pragma unroll
        for (int nt = 0; nt < 8; nt++) {
            int c0 = nt * 8 + 2 * tq;
            int kb0 = kbc[c0], kb1 = kbc[c0 + 1];
            float s0 = (kb0 == myb0) ? sacc[nt][0] * scale : -1e30f;
            float s1 = (kb1 == myb0) ? sacc[nt][1] * scale : -1e30f;
            float s2 = (kb0 == myb1) ? sacc[nt][2] * scale : -1e30f;
            float s3 = (kb1 == myb1) ? sacc[nt][3] * scale : -1e30f;
            sacc[nt][0] = s0; sacc[nt][1] = s1; sacc[nt][2] = s2; sacc[nt][3] = s3;
            rmax0 = fmaxf(rmax0, fmaxf(s0, s1));
            rmax1 = fmaxf(rmax1, fmaxf(s2, s3));
        }
        rmax0 = fmaxf(rmax0, __shfl_xor_sync(0xffffffffu, rmax0, 1));
        rmax0 = fmaxf(rmax0, __shfl_xor_sync(0xffffffffu, rmax0, 2));
        rmax1 = fmaxf(rmax1, __shfl_xor_sync(0xffffffffu, rmax1, 1));
        rmax1 = fmaxf(rmax1, __shfl_xor_sync(0xffffffffu, rmax1, 2));
        const float mn0 = fmaxf(m0, rmax0);
        const float mn1 = fmaxf(m1, rmax1);
        const float al0 = __expf(m0 - mn0);
        const float al1 = __expf(m1 - mn1);
        m0 = mn0; m1 = mn1;

        // ---- exp, pack P to bf16 pairs, update l ----
        float ls0 = 0.f, ls1 = 0.f;
        const int pr0 = (wid * 16 + g) * PSTW;
        const int pr1 = (wid * 16 + g + 8) * PSTW;
#pragma unroll
        for (int nt = 0; nt < 8; nt++) {
            float p0 = __expf(sacc[nt][0] - mn0);
            float p1 = __expf(sacc[nt][1] - mn0);
            float p2 = __expf(sacc[nt][2] - mn1);
            float p3 = __expf(sacc[nt][3] - mn1);
            ls0 += p0 + p1;
            ls1 += p2 + p3;
            Pp[pr0 + nt * 4 + tq] = pack_bf16x2(p0, p1);
            Pp[pr1 + nt * 4 + tq] = pack_bf16x2(p2, p3);
        }
        ls0 += __shfl_xor_sync(0xffffffffu, ls0, 1);
        ls0 += __shfl_xor_sync(0xffffffffu, ls0, 2);
        ls1 += __shfl_xor_sync(0xffffffffu, ls1, 1);
        ls1 += __shfl_xor_sync(0xffffffffu, ls1, 2);
        l0 = l0 * al0 + ls0;
        l1 = l1 * al1 + ls1;
#pragma unroll
        for (int nt = 0; nt < 4; nt++) {
            oacc[nt][0] *= al0; oacc[nt][1] *= al0;
            oacc[nt][2] *= al1; oacc[nt][3] *= al1;
        }
        __syncwarp();  // warp-local P rows visible

        // ---- O += P V: ldmatrix.trans V fragments; 2 key-halves x 2 k16 ----
#pragma unroll
        for (int half = 0; half < 2; half++) {
            const int key0 = half * 32;
            uint32_t vb[4][4];  // [d-block nt][key octet 0..3 within half]
#pragma unroll
            for (int nt = 0; nt < 4; nt++) {
                uint32_t addr = vsbase + ((key0 + lane) * QSTW + nt * 4) * 4;
                ldsm_x4_trans(vb[nt][0], vb[nt][1], vb[nt][2], vb[nt][3], addr);
            }
#pragma unroll
            for (int ks = 0; ks < 2; ks++) {
                const int kw = (half * 2 + ks) * 8;
                uint32_t a0 = Pp[pr0 + kw + tq];
                uint32_t a1 = Pp[pr1 + kw + tq];
                uint32_t a2 = Pp[pr0 + kw + tq + 4];
                uint32_t a3 = Pp[pr1 + kw + tq + 4];
#pragma unroll
                for (int nt = 0; nt < 4; nt++)
                    mma_bf16(oacc[nt][0], oacc[nt][1], oacc[nt][2], oacc[nt][3],
                             a0, a1, a2, a3, vb[nt][ks * 2], vb[nt][ks * 2 + 1]);
            }
        }
    }

    const float i0 = 1.f / l0;
    const float i1 = 1.f / l1;
    const int r0 = q0 + wid * 16 + g;
    const int r1 = r0 + 8;
#pragma unroll
    for (int nt = 0; nt < 4; nt++) {
        int col = h * HD + nt * 8 + 2 * tq;
        *(uint32_t*)&attn_out[(size_t)r0 * D_MODEL + col] = pack_bf16x2(oacc[nt][0] * i0, oacc[nt][1] * i0);
        *(uint32_t*)&attn_out[(size_t)r1 * D_MODEL + col] = pack_bf16x2(oacc[nt][2] * i1, oacc[nt][3] * i1);
    }
}

// ---------------- launch ----------------------------------------------------
extern "C" void kernel_launch(void* const* d_in, const int* in_sizes, int n_in,
                              void* d_out, int out_size) {
    const float* slots    = (const float*)d_in[0];
    const int*   batch_ix = (const int*)d_in[1];
    const float* w_in     = (const float*)d_in[2];
    const float* b_in     = (const float*)d_in[3];
    const float* w_out    = (const float*)d_in[4];
    const float* b_out    = (const float*)d_in[5];
    const float* ln_gamma = (const float*)d_in[6];
    const float* ln_beta  = (const float*)d_in[7];
    float* out = (float*)d_out;

    __nv_bfloat16* qkv_bf;   cudaGetSymbolAddress((void**)&qkv_bf,   g_qkv_bf);
    __nv_bfloat16* attn_bf;  cudaGetSymbolAddress((void**)&attn_bf,  g_attn_bf);
    __nv_bfloat16* slots_bf; cudaGetSymbolAddress((void**)&slots_bf, g_slots_bf);
    __nv_bfloat16* win_bf;   cudaGetSymbolAddress((void**)&win_bf,   g_win_bf);
    __nv_bfloat16* wout_bf;  cudaGetSymbolAddress((void**)&wout_bf,  g_wout_bf);

    // 0) convert inputs to bf16 (slots, w_in, w_out)
    {
        const int n0 = N_TOK * D_MODEL, n1 = QKV_W * D_MODEL, n2 = D_MODEL * D_MODEL;
        const int total4 = (n0 + n1 + n2) / 4;
        cvt_bf16_kernel<<<(total4 + 255) / 256, 256>>>(slots, slots_bf, n0,
                                                       w_in, win_bf, n1,
                                                       w_out, wout_bf, n2);
    }
    // 1) QKV projection (bf16 in/out): qkv = slots @ w_in^T + b_in
    {
        dim3 grid(QKV_W / GBN, N_TOK / GBM);
        gemm_bf16_kernel<<<grid, 256>>>(slots_bf, win_bf, b_in, qkv_bf,
                                        N_TOK, QKV_W, D_MODEL);
    }
    // 2) block-diagonal flash attention (bf16 mma, pipelined K/V)
    {
        dim3 grid(N_TOK / QT, H_HEADS);
        flash_attn_kernel<<<grid, 128>>>(qkv_bf, batch_ix, attn_bf);
    }
    // 3) fused out-projection + bias + residual + LayerNorm (512 threads)
    {
        const int smem_bytes = G2WORDS * (int)sizeof(uint32_t);  // ~103 KB
        cudaFuncSetAttribute(gemm2_ln_kernel,
                             cudaFuncAttributeMaxDynamicSharedMemorySize, smem_bytes);
        gemm2_ln_kernel<<<N_TOK / G2BM, 512, smem_bytes>>>(attn_bf, wout_bf, b_out, slots,
                                                           ln_gamma, ln_beta, out);
    }
}